// round 1
// baseline (speedup 1.0000x reference)
#include <cuda_runtime.h>

// ---------------- problem constants ----------------
#define NN   50000
#define EE   800000
#define ET   (EE + NN)      // edges + self loops = 850000
#define HEADS 4
#define HC   256            // HEADS * 64
#define CC   64
#define NEG  0.2f

// ---------------- device scratch (static, no allocs) ----------------
__device__ float    g_h  [(size_t)NN * HC];   // per-layer hidden [N,256]
__device__ float    g_as [NN * 4];            // alpha_src [N,H]
__device__ float    g_ad [NN * 4];            // alpha_dst [N,H]
__device__ unsigned g_m  [NN * 4];            // segment max (ordered-uint encoding)
__device__ float    g_den[NN * 4];            // segment sum of exp
__device__ float    g_ex [(size_t)ET * 4];    // per-edge exp values
__device__ float    g_x2 [(size_t)NN * CC];   // layer1 output / layer2 input
__device__ int      g_is64;                   // edge_index dtype flag

// ---------------- helpers ----------------
__device__ __forceinline__ unsigned ford(float f) {
    unsigned u = __float_as_uint(f);
    return (u & 0x80000000u) ? ~u : (u | 0x80000000u);
}
__device__ __forceinline__ float forddec(unsigned v) {
    return (v & 0x80000000u) ? __uint_as_float(v & 0x7FFFFFFFu)
                             : __uint_as_float(~v);
}
__device__ __forceinline__ void edge_sd(const void* ei, int e, int& s, int& d) {
    if (e < EE) {
        if (g_is64) {
            const long long* p = (const long long*)ei;
            s = (int)p[e]; d = (int)p[EE + e];
        } else {
            const int* p = (const int*)ei;
            s = p[e]; d = p[EE + e];
        }
    } else {
        s = d = e - EE;   // self loop
    }
}

// Detect whether edge_index is int64 (odd 32-bit words all zero) or int32.
__global__ void detect_idx_kernel(const int* __restrict__ words) {
    __shared__ int any;
    if (threadIdx.x == 0) any = 0;
    __syncthreads();
    for (int i = threadIdx.x; i < 1024; i += blockDim.x)
        if (words[2 * i + 1] != 0) any = 1;
    __syncthreads();
    if (threadIdx.x == 0) g_is64 = any ? 0 : 1;
}

// ---------------- GEMM: H[n, 256] = X[n, :K] @ W[256, :K]^T ----------------
template <int K>
__global__ void gemm_nt_kernel(const float* __restrict__ X,
                               const float* __restrict__ W,
                               int n_rows) {
    const int BM = 64, BN = 64, BK = 32;
    __shared__ float Xs[BM][BK + 1];
    __shared__ float Ws[BN][BK + 1];

    int bm = blockIdx.x * BM;
    int bn = blockIdx.y * BN;
    int tid = threadIdx.x;            // 256 threads
    int tx = tid & 15, ty = tid >> 4; // 16x16 thread grid, 4x4 micro-tile

    float acc[4][4] = {};

    for (int kt = 0; kt < K; kt += BK) {
        #pragma unroll
        for (int i = 0; i < 8; i++) {
            int lin = tid + i * 256;          // 2048 elements
            int r = lin >> 5, c = lin & 31;
            int row = bm + r;
            Xs[r][c] = (row < n_rows) ? X[(size_t)row * K + kt + c] : 0.0f;
            Ws[r][c] = W[(size_t)(bn + r) * K + kt + c];
        }
        __syncthreads();

        #pragma unroll
        for (int k = 0; k < BK; k++) {
            float xr[4], wc[4];
            #pragma unroll
            for (int i = 0; i < 4; i++) xr[i] = Xs[ty * 4 + i][k];
            #pragma unroll
            for (int j = 0; j < 4; j++) wc[j] = Ws[tx * 4 + j][k];
            #pragma unroll
            for (int i = 0; i < 4; i++)
                #pragma unroll
                for (int j = 0; j < 4; j++)
                    acc[i][j] += xr[i] * wc[j];
        }
        __syncthreads();
    }

    #pragma unroll
    for (int i = 0; i < 4; i++) {
        int row = bm + ty * 4 + i;
        if (row >= n_rows) continue;
        #pragma unroll
        for (int j = 0; j < 4; j++)
            g_h[(size_t)row * HC + bn + tx * 4 + j] = acc[i][j];
    }
}

// ---------------- alpha: as[n,h] = <h[n,h,:], a_src[h,:]>, same for dst ----
__global__ void alpha_kernel(const float* __restrict__ a_src,
                             const float* __restrict__ a_dst) {
    int warp = (blockIdx.x * blockDim.x + threadIdx.x) >> 5;
    int lane = threadIdx.x & 31;
    if (warp >= NN) return;
    const float* hr = g_h + (size_t)warp * HC;
    #pragma unroll
    for (int h = 0; h < 4; h++) {
        float v0 = hr[h * 64 + lane];
        float v1 = hr[h * 64 + 32 + lane];
        float s = v0 * a_src[h * 64 + lane] + v1 * a_src[h * 64 + 32 + lane];
        float d = v0 * a_dst[h * 64 + lane] + v1 * a_dst[h * 64 + 32 + lane];
        #pragma unroll
        for (int o = 16; o > 0; o >>= 1) {
            s += __shfl_xor_sync(0xFFFFFFFFu, s, o);
            d += __shfl_xor_sync(0xFFFFFFFFu, d, o);
        }
        if (lane == 0) {
            g_as[warp * 4 + h] = s;
            g_ad[warp * 4 + h] = d;
        }
    }
}

// ---------------- edge phase 1: segment max ----------------
__global__ void edge_max_kernel(const void* __restrict__ ei) {
    int e = blockIdx.x * blockDim.x + threadIdx.x;
    if (e >= ET) return;
    int s, d;
    edge_sd(ei, e, s, d);
    float4 as = *(const float4*)(g_as + s * 4);
    float4 ad = *(const float4*)(g_ad + d * 4);
    unsigned* md = g_m + d * 4;
    float v;
    v = as.x + ad.x; v = v > 0.f ? v : NEG * v; atomicMax(&md[0], ford(v));
    v = as.y + ad.y; v = v > 0.f ? v : NEG * v; atomicMax(&md[1], ford(v));
    v = as.z + ad.z; v = v > 0.f ? v : NEG * v; atomicMax(&md[2], ford(v));
    v = as.w + ad.w; v = v > 0.f ? v : NEG * v; atomicMax(&md[3], ford(v));
}

// ---------------- edge phase 2: exp + segment sum ----------------
__global__ void edge_exp_kernel(const void* __restrict__ ei) {
    int e = blockIdx.x * blockDim.x + threadIdx.x;
    if (e >= ET) return;
    int s, d;
    edge_sd(ei, e, s, d);
    float4 as = *(const float4*)(g_as + s * 4);
    float4 ad = *(const float4*)(g_ad + d * 4);
    float4 ex;
    float v;
    v = as.x + ad.x; v = v > 0.f ? v : NEG * v; ex.x = __expf(v - forddec(g_m[d * 4 + 0]));
    v = as.y + ad.y; v = v > 0.f ? v : NEG * v; ex.y = __expf(v - forddec(g_m[d * 4 + 1]));
    v = as.z + ad.z; v = v > 0.f ? v : NEG * v; ex.z = __expf(v - forddec(g_m[d * 4 + 2]));
    v = as.w + ad.w; v = v > 0.f ? v : NEG * v; ex.w = __expf(v - forddec(g_m[d * 4 + 3]));
    *(float4*)(g_ex + (size_t)e * 4) = ex;
    atomicAdd(&g_den[d * 4 + 0], ex.x);
    atomicAdd(&g_den[d * 4 + 1], ex.y);
    atomicAdd(&g_den[d * 4 + 2], ex.z);
    atomicAdd(&g_den[d * 4 + 3], ex.w);
}

// ---------------- edge phase 3: weighted scatter (head mean fused) --------
__global__ void scatter_kernel(const void* __restrict__ ei,
                               float* __restrict__ acc) {
    int gw = (blockIdx.x * blockDim.x + threadIdx.x) >> 5;
    int lane = threadIdx.x & 31;
    if (gw >= ET) return;
    int s, d;
    edge_sd(ei, gw, s, d);
    float4 ex  = *(const float4*)(g_ex  + (size_t)gw * 4);
    float4 den = *(const float4*)(g_den + d * 4);
    float w0 = ex.x / (den.x + 1e-16f) * 0.25f;
    float w1 = ex.y / (den.y + 1e-16f) * 0.25f;
    float w2 = ex.z / (den.z + 1e-16f) * 0.25f;
    float w3 = ex.w / (den.w + 1e-16f) * 0.25f;
    const float2* hr = (const float2*)(g_h + (size_t)s * HC);
    float2 a = hr[lane], b = hr[32 + lane], c = hr[64 + lane], e2 = hr[96 + lane];
    float ox = a.x * w0 + b.x * w1 + c.x * w2 + e2.x * w3;
    float oy = a.y * w0 + b.y * w1 + c.y * w2 + e2.y * w3;
    atomicAdd(acc + (size_t)d * CC + 2 * lane,     ox);
    atomicAdd(acc + (size_t)d * CC + 2 * lane + 1, oy);
}

// ---------------- finalize layer 1: elu(acc + b1) in place ----------------
__global__ void finalize1_kernel(const float* __restrict__ b1) {
    int i = blockIdx.x * blockDim.x + threadIdx.x;
    if (i >= NN * CC) return;
    float v = g_x2[i] + b1[i & (CC - 1)];
    g_x2[i] = v > 0.f ? v : expm1f(v);
}

// ---------------- finalize layer 2: out += b2 ----------------
__global__ void finalize2_kernel(float* __restrict__ out,
                                 const float* __restrict__ b2) {
    int i = blockIdx.x * blockDim.x + threadIdx.x;
    if (i >= NN * CC) return;
    out[i] += b2[i & (CC - 1)];
}

// ---------------- host launch ----------------
extern "C" void kernel_launch(void* const* d_in, const int* in_sizes, int n_in,
                              void* d_out, int out_size) {
    const float* x      = (const float*)d_in[0];
    const void*  ei     = d_in[1];
    const float* W1     = (const float*)d_in[2];
    const float* a_src1 = (const float*)d_in[3];
    const float* a_dst1 = (const float*)d_in[4];
    const float* b1     = (const float*)d_in[5];
    const float* W2     = (const float*)d_in[6];
    const float* a_src2 = (const float*)d_in[7];
    const float* a_dst2 = (const float*)d_in[8];
    const float* b2     = (const float*)d_in[9];
    float* out = (float*)d_out;

    void *p_m, *p_den, *p_x2;
    cudaGetSymbolAddress(&p_m,   g_m);
    cudaGetSymbolAddress(&p_den, g_den);
    cudaGetSymbolAddress(&p_x2,  g_x2);

    const int TB = 256;
    dim3 gemm_grid((NN + 63) / 64, HC / 64);
    int alpha_blocks = (NN * 32 + TB - 1) / TB;
    int edge_blocks  = (ET + TB - 1) / TB;
    int scat_blocks  = (ET * 32 + TB - 1) / TB;
    int fin_blocks   = (NN * CC + TB - 1) / TB;

    detect_idx_kernel<<<1, 256>>>((const int*)ei);

    // -------- layer 1 --------
    gemm_nt_kernel<128><<<gemm_grid, TB>>>(x, W1, NN);
    alpha_kernel<<<alpha_blocks, TB>>>(a_src1, a_dst1);
    cudaMemsetAsync(p_m,   0, (size_t)NN * 4 * sizeof(unsigned), 0);
    cudaMemsetAsync(p_den, 0, (size_t)NN * 4 * sizeof(float), 0);
    edge_max_kernel<<<edge_blocks, TB>>>(ei);
    edge_exp_kernel<<<edge_blocks, TB>>>(ei);
    cudaMemsetAsync(p_x2, 0, (size_t)NN * CC * sizeof(float), 0);
    scatter_kernel<<<scat_blocks, TB>>>(ei, (float*)p_x2);
    finalize1_kernel<<<fin_blocks, TB>>>(b1);

    // -------- layer 2 --------
    gemm_nt_kernel<64><<<gemm_grid, TB>>>((const float*)p_x2, W2, NN);
    alpha_kernel<<<alpha_blocks, TB>>>(a_src2, a_dst2);
    cudaMemsetAsync(p_m,   0, (size_t)NN * 4 * sizeof(unsigned), 0);
    cudaMemsetAsync(p_den, 0, (size_t)NN * 4 * sizeof(float), 0);
    edge_max_kernel<<<edge_blocks, TB>>>(ei);
    edge_exp_kernel<<<edge_blocks, TB>>>(ei);
    cudaMemsetAsync(out, 0, (size_t)NN * CC * sizeof(float), 0);
    scatter_kernel<<<scat_blocks, TB>>>(ei, out);
    finalize2_kernel<<<fin_blocks, TB>>>(out, b2);
}

// round 2
// speedup vs baseline: 1.4598x; 1.4598x over previous
#include <cuda_runtime.h>

// ---------------- problem constants ----------------
#define NN   50000
#define EE   800000
#define ET   (EE + NN)      // edges + self loops = 850000
#define HC   256            // HEADS * 64
#define CC   64
#define NEG  0.2f
#define SCAN_BS 256
#define NB   ((NN + SCAN_BS - 1) / SCAN_BS)   // 196

// ---------------- device scratch (static, no allocs) ----------------
__device__ float g_h  [(size_t)NN * HC];   // hidden [N,256]
__device__ float g_as [NN * 4];            // alpha_src [N,H]
__device__ float g_ad [NN * 4];            // alpha_dst [N,H]
__device__ float g_den[NN * 4];            // per-dst softmax denom
__device__ float g_w  [(size_t)ET * 4];    // per-edge logits -> exp (CSR order)
__device__ float g_x2 [(size_t)NN * CC];   // layer1 output
__device__ int   g_srcs[ET];               // CSR: src of each edge, grouped by dst
__device__ int   g_cnt[NN];
__device__ int   g_cur[NN];
__device__ int   g_off[NN + 1];
__device__ int   g_part[SCAN_BS];
__device__ int   g_is64;

// ---------------- helpers ----------------
__device__ __forceinline__ void edge_sd(const void* ei, int e, int& s, int& d) {
    if (e < EE) {
        if (g_is64) {
            const long long* p = (const long long*)ei;
            s = (int)p[e]; d = (int)p[EE + e];
        } else {
            const int* p = (const int*)ei;
            s = p[e]; d = p[EE + e];
        }
    } else {
        s = d = e - EE;   // self loop
    }
}

__global__ void detect_idx_kernel(const int* __restrict__ words) {
    __shared__ int any;
    if (threadIdx.x == 0) any = 0;
    __syncthreads();
    for (int i = threadIdx.x; i < 1024; i += blockDim.x)
        if (words[2 * i + 1] != 0) any = 1;
    __syncthreads();
    if (threadIdx.x == 0) g_is64 = any ? 0 : 1;
}

// ---------------- CSR build ----------------
__global__ void hist_kernel(const void* __restrict__ ei) {
    int e = blockIdx.x * blockDim.x + threadIdx.x;
    if (e >= ET) return;
    int s, d; edge_sd(ei, e, s, d);
    atomicAdd(&g_cnt[d], 1);
}

__global__ void csr_block_sums() {
    __shared__ int sd[256];
    int t = threadIdx.x;
    int i = blockIdx.x * 256 + t;
    sd[t] = (i < NN) ? g_cnt[i] : 0;
    __syncthreads();
    for (int o = 128; o > 0; o >>= 1) {
        if (t < o) sd[t] += sd[t + o];
        __syncthreads();
    }
    if (t == 0) g_part[blockIdx.x] = sd[0];
}

__global__ void csr_scan_part() {
    __shared__ int sd[256];
    int t = threadIdx.x;
    int v = (t < NB) ? g_part[t] : 0;
    sd[t] = v;
    __syncthreads();
    for (int o = 1; o < 256; o <<= 1) {
        int x = (t >= o) ? sd[t - o] : 0;
        __syncthreads();
        sd[t] += x;
        __syncthreads();
    }
    if (t < NB) g_part[t] = sd[t] - v;   // exclusive
    if (t == 0) g_off[NN] = ET;
}

__global__ void csr_offsets() {
    __shared__ int sd[256];
    int t = threadIdx.x;
    int i = blockIdx.x * 256 + t;
    int v = (i < NN) ? g_cnt[i] : 0;
    sd[t] = v;
    __syncthreads();
    for (int o = 1; o < 256; o <<= 1) {
        int x = (t >= o) ? sd[t - o] : 0;
        __syncthreads();
        sd[t] += x;
        __syncthreads();
    }
    if (i < NN) g_off[i] = sd[t] - v + g_part[blockIdx.x];
}

__global__ void fill_kernel(const void* __restrict__ ei) {
    int e = blockIdx.x * blockDim.x + threadIdx.x;
    if (e >= ET) return;
    int s, d; edge_sd(ei, e, s, d);
    int pos = g_off[d] + atomicAdd(&g_cur[d], 1);
    g_srcs[pos] = s;
}

// ---------------- GEMM: H[n, 256] = X @ W^T via fma.rn.f32x2 -------------
__device__ __forceinline__ unsigned long long pack2(float x, float y) {
    unsigned long long r;
    asm("mov.b64 %0, {%1, %2};" : "=l"(r) : "f"(x), "f"(y));
    return r;
}
__device__ __forceinline__ void ffma2(unsigned long long& acc,
                                      unsigned long long a, unsigned long long b) {
    asm("fma.rn.f32x2 %0, %1, %2, %0;" : "+l"(acc) : "l"(a), "l"(b));
}

template <int K>
__global__ void gemm_nt_kernel(const float* __restrict__ X,
                               const float* __restrict__ W) {
    const int BM = 128, BN = 64, BK = 16;
    __shared__ float Xs[BM * (BK + 1)];     // [r][k], pad 17
    __shared__ float Wst[BK * (BN + 2)];    // [k][c], pad 66 (keeps float2 align)

    int bm = blockIdx.x * BM, bn = blockIdx.y * BN;
    int tid = threadIdx.x;                  // 256 threads
    int tx = tid & 15, ty = tid >> 4;       // 16x16; micro-tile 8 rows x 4 cols

    unsigned long long acc[8][2];
    #pragma unroll
    for (int i = 0; i < 8; i++) { acc[i][0] = 0ull; acc[i][1] = 0ull; }

    for (int kt = 0; kt < K; kt += BK) {
        #pragma unroll
        for (int l = 0; l < 8; l++) {       // X tile: 128x16 = 2048
            int lin = tid + l * 256;
            int k = lin & 15, r = lin >> 4;
            int row = bm + r;
            Xs[r * (BK + 1) + k] = (row < NN) ? X[(size_t)row * K + kt + k] : 0.0f;
        }
        #pragma unroll
        for (int l = 0; l < 4; l++) {       // W tile transposed: 16x64 = 1024
            int lin = tid + l * 256;
            int k = lin & 15, c = lin >> 4;
            Wst[k * (BN + 2) + c] = W[(size_t)(bn + c) * K + kt + k];
        }
        __syncthreads();

        #pragma unroll
        for (int k = 0; k < BK; k++) {
            unsigned long long wp0 = *(const unsigned long long*)&Wst[k * (BN + 2) + tx * 4];
            unsigned long long wp1 = *(const unsigned long long*)&Wst[k * (BN + 2) + tx * 4 + 2];
            #pragma unroll
            for (int i = 0; i < 8; i++) {
                float x = Xs[(ty * 8 + i) * (BK + 1) + k];
                unsigned long long xp = pack2(x, x);
                ffma2(acc[i][0], xp, wp0);
                ffma2(acc[i][1], xp, wp1);
            }
        }
        __syncthreads();
    }

    #pragma unroll
    for (int i = 0; i < 8; i++) {
        int row = bm + ty * 8 + i;
        if (row >= NN) continue;
        *(unsigned long long*)&g_h[(size_t)row * HC + bn + tx * 4]     = acc[i][0];
        *(unsigned long long*)&g_h[(size_t)row * HC + bn + tx * 4 + 2] = acc[i][1];
    }
}

// ---------------- alpha dot products ----------------
__global__ void alpha_kernel(const float* __restrict__ a_src,
                             const float* __restrict__ a_dst) {
    int warp = (blockIdx.x * blockDim.x + threadIdx.x) >> 5;
    int lane = threadIdx.x & 31;
    if (warp >= NN) return;
    const float* hr = g_h + (size_t)warp * HC;
    #pragma unroll
    for (int h = 0; h < 4; h++) {
        float v0 = hr[h * 64 + lane];
        float v1 = hr[h * 64 + 32 + lane];
        float s = v0 * a_src[h * 64 + lane] + v1 * a_src[h * 64 + 32 + lane];
        float d = v0 * a_dst[h * 64 + lane] + v1 * a_dst[h * 64 + 32 + lane];
        #pragma unroll
        for (int o = 16; o > 0; o >>= 1) {
            s += __shfl_xor_sync(0xFFFFFFFFu, s, o);
            d += __shfl_xor_sync(0xFFFFFFFFu, d, o);
        }
        if (lane == 0) {
            g_as[warp * 4 + h] = s;
            g_ad[warp * 4 + h] = d;
        }
    }
}

// ---------------- per-dst softmax over CSR (no atomics) ----------------
__global__ void softmax_kernel() {
    int w = (blockIdx.x * blockDim.x + threadIdx.x) >> 5;
    int lane = threadIdx.x & 31;
    if (w >= NN) return;
    int beg = g_off[w], end = g_off[w + 1];
    float4 ad = *(const float4*)(g_ad + w * 4);
    float m0 = -1e30f, m1 = -1e30f, m2 = -1e30f, m3 = -1e30f;
    for (int i = beg + lane; i < end; i += 32) {
        int s = g_srcs[i];
        float4 as = *(const float4*)(g_as + s * 4);
        float e0 = as.x + ad.x; e0 = e0 > 0.f ? e0 : NEG * e0;
        float e1 = as.y + ad.y; e1 = e1 > 0.f ? e1 : NEG * e1;
        float e2 = as.z + ad.z; e2 = e2 > 0.f ? e2 : NEG * e2;
        float e3 = as.w + ad.w; e3 = e3 > 0.f ? e3 : NEG * e3;
        *(float4*)(g_w + (size_t)i * 4) = make_float4(e0, e1, e2, e3);
        m0 = fmaxf(m0, e0); m1 = fmaxf(m1, e1);
        m2 = fmaxf(m2, e2); m3 = fmaxf(m3, e3);
    }
    #pragma unroll
    for (int o = 16; o > 0; o >>= 1) {
        m0 = fmaxf(m0, __shfl_xor_sync(0xFFFFFFFFu, m0, o));
        m1 = fmaxf(m1, __shfl_xor_sync(0xFFFFFFFFu, m1, o));
        m2 = fmaxf(m2, __shfl_xor_sync(0xFFFFFFFFu, m2, o));
        m3 = fmaxf(m3, __shfl_xor_sync(0xFFFFFFFFu, m3, o));
    }
    float d0 = 0.f, d1 = 0.f, d2 = 0.f, d3 = 0.f;
    for (int i = beg + lane; i < end; i += 32) {
        float4 e = *(const float4*)(g_w + (size_t)i * 4);
        e.x = __expf(e.x - m0); e.y = __expf(e.y - m1);
        e.z = __expf(e.z - m2); e.w = __expf(e.w - m3);
        *(float4*)(g_w + (size_t)i * 4) = e;
        d0 += e.x; d1 += e.y; d2 += e.z; d3 += e.w;
    }
    #pragma unroll
    for (int o = 16; o > 0; o >>= 1) {
        d0 += __shfl_xor_sync(0xFFFFFFFFu, d0, o);
        d1 += __shfl_xor_sync(0xFFFFFFFFu, d1, o);
        d2 += __shfl_xor_sync(0xFFFFFFFFu, d2, o);
        d3 += __shfl_xor_sync(0xFFFFFFFFu, d3, o);
    }
    if (lane == 0)
        *(float4*)(g_den + w * 4) = make_float4(d0, d1, d2, d3);
}

// ---------------- per-dst aggregate: gather + register acc, 1 store ------
template <int ACT>
__global__ void aggregate_kernel(float* __restrict__ out,
                                 const float* __restrict__ bias) {
    int d = (blockIdx.x * blockDim.x + threadIdx.x) >> 5;
    int lane = threadIdx.x & 31;
    if (d >= NN) return;
    int beg = g_off[d], end = g_off[d + 1];
    float4 den = *(const float4*)(g_den + d * 4);
    float i0 = 0.25f / (den.x + 1e-16f);
    float i1 = 0.25f / (den.y + 1e-16f);
    float i2 = 0.25f / (den.z + 1e-16f);
    float i3 = 0.25f / (den.w + 1e-16f);

    float ox = 0.f, oy = 0.f;
    int s = g_srcs[beg];
    float4 e4 = *(const float4*)(g_w + (size_t)beg * 4);
    for (int i = beg; i < end; i++) {
        int sn = 0;
        float4 en = make_float4(0.f, 0.f, 0.f, 0.f);
        if (i + 1 < end) {                 // prefetch next edge (breaks chain)
            sn = g_srcs[i + 1];
            en = *(const float4*)(g_w + (size_t)(i + 1) * 4);
        }
        float w0 = e4.x * i0, w1 = e4.y * i1, w2 = e4.z * i2, w3 = e4.w * i3;
        const float2* hr = (const float2*)(g_h + (size_t)s * HC);
        float2 a = hr[lane], b = hr[32 + lane], c = hr[64 + lane], f = hr[96 + lane];
        ox += a.x * w0 + b.x * w1 + c.x * w2 + f.x * w3;
        oy += a.y * w0 + b.y * w1 + c.y * w2 + f.y * w3;
        s = sn; e4 = en;
    }
    float2 bv = ((const float2*)bias)[lane];
    ox += bv.x; oy += bv.y;
    if (ACT) {
        ox = ox > 0.f ? ox : expm1f(ox);
        oy = oy > 0.f ? oy : expm1f(oy);
    }
    float2 r; r.x = ox; r.y = oy;
    *(float2*)(out + (size_t)d * CC + 2 * lane) = r;
}

// ---------------- host launch ----------------
extern "C" void kernel_launch(void* const* d_in, const int* in_sizes, int n_in,
                              void* d_out, int out_size) {
    const float* x      = (const float*)d_in[0];
    const void*  ei     = d_in[1];
    const float* W1     = (const float*)d_in[2];
    const float* a_src1 = (const float*)d_in[3];
    const float* a_dst1 = (const float*)d_in[4];
    const float* b1     = (const float*)d_in[5];
    const float* W2     = (const float*)d_in[6];
    const float* a_src2 = (const float*)d_in[7];
    const float* a_dst2 = (const float*)d_in[8];
    const float* b2     = (const float*)d_in[9];
    float* out = (float*)d_out;

    void *p_cnt, *p_cur, *p_x2;
    cudaGetSymbolAddress(&p_cnt, g_cnt);
    cudaGetSymbolAddress(&p_cur, g_cur);
    cudaGetSymbolAddress(&p_x2,  g_x2);

    const int TB = 256;
    dim3 gemm_grid((NN + 127) / 128, HC / 64);
    int warp_blocks = (NN * 32 + TB - 1) / TB;
    int edge_blocks = (ET + TB - 1) / TB;

    detect_idx_kernel<<<1, 256>>>((const int*)ei);

    // -------- CSR build (shared by both layers) --------
    cudaMemsetAsync(p_cnt, 0, NN * sizeof(int), 0);
    cudaMemsetAsync(p_cur, 0, NN * sizeof(int), 0);
    hist_kernel<<<edge_blocks, TB>>>(ei);
    csr_block_sums<<<NB, 256>>>();
    csr_scan_part<<<1, 256>>>();
    csr_offsets<<<NB, 256>>>();
    fill_kernel<<<edge_blocks, TB>>>(ei);

    // -------- layer 1 --------
    gemm_nt_kernel<128><<<gemm_grid, TB>>>(x, W1);
    alpha_kernel<<<warp_blocks, TB>>>(a_src1, a_dst1);
    softmax_kernel<<<warp_blocks, TB>>>();
    aggregate_kernel<1><<<warp_blocks, TB>>>((float*)p_x2, b1);

    // -------- layer 2 --------
    gemm_nt_kernel<64><<<gemm_grid, TB>>>((const float*)p_x2, W2);
    alpha_kernel<<<warp_blocks, TB>>>(a_src2, a_dst2);
    softmax_kernel<<<warp_blocks, TB>>>();
    aggregate_kernel<0><<<warp_blocks, TB>>>(out, b2);
}

// round 3
// speedup vs baseline: 1.8111x; 1.2407x over previous
#include <cuda_runtime.h>
#include <cuda_fp16.h>

// ---------------- problem constants ----------------
#define NN   50000
#define EE   800000
#define ET   (EE + NN)      // edges + self loops = 850000
#define HC   256            // HEADS * 64
#define CC   64
#define NEG  0.2f
#define SCAN_BS 256
#define NB   ((NN + SCAN_BS - 1) / SCAN_BS)   // 196

// ---------------- device scratch (static, no allocs) ----------------
__device__ __half g_hh [(size_t)NN * HC];  // hidden, fp16, [N,256]
__device__ float  g_as [NN * 4];           // alpha_src [N,H] (fp32, from GEMM epilogue)
__device__ float  g_ad [NN * 4];           // alpha_dst [N,H]
__device__ float  g_w  [(size_t)ET * 4];   // per-edge exp values (CSR order)
__device__ float  g_x2 [(size_t)NN * CC];  // layer1 output (fp32)
__device__ int    g_srcs[ET];              // CSR: src per edge, grouped by dst
__device__ int    g_cnt[NN];
__device__ int    g_cur[NN];
__device__ int    g_off[NN + 1];
__device__ int    g_part[SCAN_BS];
__device__ int    g_is64;

// ---------------- helpers ----------------
__device__ __forceinline__ void edge_sd(const void* ei, int e, int& s, int& d) {
    if (e < EE) {
        if (g_is64) {
            const long long* p = (const long long*)ei;
            s = (int)p[e]; d = (int)p[EE + e];
        } else {
            const int* p = (const int*)ei;
            s = p[e]; d = p[EE + e];
        }
    } else {
        s = d = e - EE;   // self loop
    }
}

__global__ void detect_idx_kernel(const int* __restrict__ words) {
    __shared__ int any;
    if (threadIdx.x == 0) any = 0;
    __syncthreads();
    for (int i = threadIdx.x; i < 1024; i += blockDim.x)
        if (words[2 * i + 1] != 0) any = 1;
    __syncthreads();
    if (threadIdx.x == 0) g_is64 = any ? 0 : 1;
}

// ---------------- CSR build ----------------
__global__ void hist_kernel(const void* __restrict__ ei) {
    int e = blockIdx.x * blockDim.x + threadIdx.x;
    if (e >= ET) return;
    int s, d; edge_sd(ei, e, s, d);
    atomicAdd(&g_cnt[d], 1);
}

__global__ void csr_block_sums() {
    __shared__ int sd[256];
    int t = threadIdx.x;
    int i = blockIdx.x * 256 + t;
    sd[t] = (i < NN) ? g_cnt[i] : 0;
    __syncthreads();
    for (int o = 128; o > 0; o >>= 1) {
        if (t < o) sd[t] += sd[t + o];
        __syncthreads();
    }
    if (t == 0) g_part[blockIdx.x] = sd[0];
}

__global__ void csr_scan_part() {
    __shared__ int sd[256];
    int t = threadIdx.x;
    int v = (t < NB) ? g_part[t] : 0;
    sd[t] = v;
    __syncthreads();
    for (int o = 1; o < 256; o <<= 1) {
        int x = (t >= o) ? sd[t - o] : 0;
        __syncthreads();
        sd[t] += x;
        __syncthreads();
    }
    if (t < NB) g_part[t] = sd[t] - v;   // exclusive
    if (t == 0) g_off[NN] = ET;
}

__global__ void csr_offsets() {
    __shared__ int sd[256];
    int t = threadIdx.x;
    int i = blockIdx.x * 256 + t;
    int v = (i < NN) ? g_cnt[i] : 0;
    sd[t] = v;
    __syncthreads();
    for (int o = 1; o < 256; o <<= 1) {
        int x = (t >= o) ? sd[t - o] : 0;
        __syncthreads();
        sd[t] += x;
        __syncthreads();
    }
    if (i < NN) g_off[i] = sd[t] - v + g_part[blockIdx.x];
}

__global__ void fill_kernel(const void* __restrict__ ei) {
    int e = blockIdx.x * blockDim.x + threadIdx.x;
    if (e >= ET) return;
    int s, d; edge_sd(ei, e, s, d);
    int pos = g_off[d] + atomicAdd(&g_cur[d], 1);
    g_srcs[pos] = s;
}

// ---------------- GEMM + fused alpha epilogue + fp16 store ----------------
__device__ __forceinline__ unsigned long long pack2(float x, float y) {
    unsigned long long r;
    asm("mov.b64 %0, {%1, %2};" : "=l"(r) : "f"(x), "f"(y));
    return r;
}
__device__ __forceinline__ void unpack2(unsigned long long v, float& x, float& y) {
    asm("mov.b64 {%0, %1}, %2;" : "=f"(x), "=f"(y) : "l"(v));
}
__device__ __forceinline__ void ffma2(unsigned long long& acc,
                                      unsigned long long a, unsigned long long b) {
    asm("fma.rn.f32x2 %0, %1, %2, %0;" : "+l"(acc) : "l"(a), "l"(b));
}

template <int K>
__global__ void gemm_nt_kernel(const float* __restrict__ X,
                               const float* __restrict__ W,
                               const float* __restrict__ a_src,
                               const float* __restrict__ a_dst) {
    const int BM = 128, BN = 64, BK = 16;
    __shared__ float Xs[BM * (BK + 1)];
    __shared__ float Wst[BK * (BN + 2)];

    int bm = blockIdx.x * BM, bn = blockIdx.y * BN;   // bn = head*64
    int tid = threadIdx.x;                  // 256 threads
    int tx = tid & 15, ty = tid >> 4;       // micro-tile 8 rows x 4 cols

    unsigned long long acc[8][2];
    #pragma unroll
    for (int i = 0; i < 8; i++) { acc[i][0] = 0ull; acc[i][1] = 0ull; }

    for (int kt = 0; kt < K; kt += BK) {
        #pragma unroll
        for (int l = 0; l < 8; l++) {       // X tile: 128x16
            int lin = tid + l * 256;
            int k = lin & 15, r = lin >> 4;
            int row = bm + r;
            Xs[r * (BK + 1) + k] = (row < NN) ? X[(size_t)row * K + kt + k] : 0.0f;
        }
        #pragma unroll
        for (int l = 0; l < 4; l++) {       // W tile transposed: 16x64
            int lin = tid + l * 256;
            int k = lin & 15, c = lin >> 4;
            Wst[k * (BN + 2) + c] = W[(size_t)(bn + c) * K + kt + k];
        }
        __syncthreads();

        #pragma unroll
        for (int k = 0; k < BK; k++) {
            unsigned long long wp0 = *(const unsigned long long*)&Wst[k * (BN + 2) + tx * 4];
            unsigned long long wp1 = *(const unsigned long long*)&Wst[k * (BN + 2) + tx * 4 + 2];
            #pragma unroll
            for (int i = 0; i < 8; i++) {
                float x = Xs[(ty * 8 + i) * (BK + 1) + k];
                unsigned long long xp = pack2(x, x);
                ffma2(acc[i][0], xp, wp0);
                ffma2(acc[i][1], xp, wp1);
            }
        }
        __syncthreads();
    }

    // ---- epilogue: fp16 store + alpha dot products ----
    float4 asv = *(const float4*)&a_src[bn + tx * 4];
    float4 adv = *(const float4*)&a_dst[bn + tx * 4];
    int head = bn >> 6;

    #pragma unroll
    for (int i = 0; i < 8; i++) {
        int row = bm + ty * 8 + i;
        float f0, f1, f2, f3;
        unpack2(acc[i][0], f0, f1);
        unpack2(acc[i][1], f2, f3);

        if (row < NN) {
            __half2 p0 = __floats2half2_rn(f0, f1);
            __half2 p1 = __floats2half2_rn(f2, f3);
            uint2 u;
            u.x = *(unsigned*)&p0; u.y = *(unsigned*)&p1;
            *(uint2*)&g_hh[(size_t)row * HC + bn + tx * 4] = u;
        }

        float s = f0 * asv.x + f1 * asv.y + f2 * asv.z + f3 * asv.w;
        float d = f0 * adv.x + f1 * adv.y + f2 * adv.z + f3 * adv.w;
        #pragma unroll
        for (int o = 8; o > 0; o >>= 1) {   // reduce over 16 tx lanes
            s += __shfl_xor_sync(0xFFFFFFFFu, s, o);
            d += __shfl_xor_sync(0xFFFFFFFFu, d, o);
        }
        if (tx == 0 && row < NN) {
            g_as[row * 4 + head] = s;
            g_ad[row * 4 + head] = d;
        }
    }
}

// ------- fused softmax (no max) + aggregate: one warp per destination ------
template <int ACT>
__global__ void aggregate_kernel(float* __restrict__ out,
                                 const float* __restrict__ bias) {
    int d = (blockIdx.x * blockDim.x + threadIdx.x) >> 5;
    int lane = threadIdx.x & 31;
    if (d >= NN) return;
    int beg = g_off[d], end = g_off[d + 1];
    float4 ad = *(const float4*)(g_ad + d * 4);

    // ---- pass 1: exp + denom (lane-strided) ----
    float d0 = 0.f, d1 = 0.f, d2 = 0.f, d3 = 0.f;
    for (int i = beg + lane; i < end; i += 32) {
        int s = g_srcs[i];
        float4 as = *(const float4*)(g_as + s * 4);
        float e0 = as.x + ad.x; e0 = e0 > 0.f ? e0 : NEG * e0; e0 = __expf(e0);
        float e1 = as.y + ad.y; e1 = e1 > 0.f ? e1 : NEG * e1; e1 = __expf(e1);
        float e2 = as.z + ad.z; e2 = e2 > 0.f ? e2 : NEG * e2; e2 = __expf(e2);
        float e3 = as.w + ad.w; e3 = e3 > 0.f ? e3 : NEG * e3; e3 = __expf(e3);
        *(float4*)(g_w + (size_t)i * 4) = make_float4(e0, e1, e2, e3);
        d0 += e0; d1 += e1; d2 += e2; d3 += e3;
    }
    #pragma unroll
    for (int o = 16; o > 0; o >>= 1) {
        d0 += __shfl_xor_sync(0xFFFFFFFFu, d0, o);
        d1 += __shfl_xor_sync(0xFFFFFFFFu, d1, o);
        d2 += __shfl_xor_sync(0xFFFFFFFFu, d2, o);
        d3 += __shfl_xor_sync(0xFFFFFFFFu, d3, o);
    }
    float i0 = 0.25f / (d0 + 1e-16f);
    float i1 = 0.25f / (d1 + 1e-16f);
    float i2 = 0.25f / (d2 + 1e-16f);
    float i3 = 0.25f / (d3 + 1e-16f);
    __syncwarp();   // g_w stores visible within warp

    // ---- pass 2: weighted gather-accumulate (fp16 messages) ----
    // lane < 16: heads 0,2 cols 4*lane..+3; lane >= 16: heads 1,3 same cols.
    bool hi = lane >= 16;
    float acc0 = 0.f, acc1 = 0.f, acc2 = 0.f, acc3 = 0.f;
    for (int i = beg; i < end; i++) {
        int s = g_srcs[i];
        float4 w = *(const float4*)(g_w + (size_t)i * 4);
        float wa = hi ? w.y * i1 : w.x * i0;
        float wb = hi ? w.w * i3 : w.z * i2;
        const __half2* hp = (const __half2*)(g_hh + (size_t)s * HC);
        __half2 a0 = hp[lane * 2],      a1 = hp[lane * 2 + 1];      // heads 0|1
        __half2 b0 = hp[64 + lane * 2], b1 = hp[64 + lane * 2 + 1]; // heads 2|3
        float2 fa0 = __half22float2(a0), fa1 = __half22float2(a1);
        float2 fb0 = __half22float2(b0), fb1 = __half22float2(b1);
        acc0 += fa0.x * wa + fb0.x * wb;
        acc1 += fa0.y * wa + fb0.y * wb;
        acc2 += fa1.x * wa + fb1.x * wb;
        acc3 += fa1.y * wa + fb1.y * wb;
    }
    // combine head pairs: lanes 0-15 += lanes 16-31 (same cols)
    acc0 += __shfl_down_sync(0xFFFFFFFFu, acc0, 16);
    acc1 += __shfl_down_sync(0xFFFFFFFFu, acc1, 16);
    acc2 += __shfl_down_sync(0xFFFFFFFFu, acc2, 16);
    acc3 += __shfl_down_sync(0xFFFFFFFFu, acc3, 16);

    if (lane < 16) {
        float4 bv = *(const float4*)(bias + lane * 4);
        float4 r;
        r.x = acc0 + bv.x; r.y = acc1 + bv.y;
        r.z = acc2 + bv.z; r.w = acc3 + bv.w;
        if (ACT) {
            r.x = r.x > 0.f ? r.x : expm1f(r.x);
            r.y = r.y > 0.f ? r.y : expm1f(r.y);
            r.z = r.z > 0.f ? r.z : expm1f(r.z);
            r.w = r.w > 0.f ? r.w : expm1f(r.w);
        }
        *(float4*)(out + (size_t)d * CC + lane * 4) = r;
    }
}

// ---------------- host launch ----------------
extern "C" void kernel_launch(void* const* d_in, const int* in_sizes, int n_in,
                              void* d_out, int out_size) {
    const float* x      = (const float*)d_in[0];
    const void*  ei     = d_in[1];
    const float* W1     = (const float*)d_in[2];
    const float* a_src1 = (const float*)d_in[3];
    const float* a_dst1 = (const float*)d_in[4];
    const float* b1     = (const float*)d_in[5];
    const float* W2     = (const float*)d_in[6];
    const float* a_src2 = (const float*)d_in[7];
    const float* a_dst2 = (const float*)d_in[8];
    const float* b2     = (const float*)d_in[9];
    float* out = (float*)d_out;

    void *p_cnt, *p_cur, *p_x2;
    cudaGetSymbolAddress(&p_cnt, g_cnt);
    cudaGetSymbolAddress(&p_cur, g_cur);
    cudaGetSymbolAddress(&p_x2,  g_x2);

    const int TB = 256;
    dim3 gemm_grid((NN + 127) / 128, HC / 64);
    int warp_blocks = (NN * 32 + TB - 1) / TB;
    int edge_blocks = (ET + TB - 1) / TB;

    detect_idx_kernel<<<1, 256>>>((const int*)ei);

    // -------- CSR build (shared by both layers) --------
    cudaMemsetAsync(p_cnt, 0, NN * sizeof(int), 0);
    cudaMemsetAsync(p_cur, 0, NN * sizeof(int), 0);
    hist_kernel<<<edge_blocks, TB>>>(ei);
    csr_block_sums<<<NB, 256>>>();
    csr_scan_part<<<1, 256>>>();
    csr_offsets<<<NB, 256>>>();
    fill_kernel<<<edge_blocks, TB>>>(ei);

    // -------- layer 1 --------
    gemm_nt_kernel<128><<<gemm_grid, TB>>>(x, W1, a_src1, a_dst1);
    aggregate_kernel<1><<<warp_blocks, TB>>>((float*)p_x2, b1);

    // -------- layer 2 --------
    gemm_nt_kernel<64><<<gemm_grid, TB>>>((const float*)p_x2, W2, a_src2, a_dst2);
    aggregate_kernel<0><<<warp_blocks, TB>>>(out, b2);
}

// round 4
// speedup vs baseline: 1.8334x; 1.0123x over previous
#include <cuda_runtime.h>
#include <cuda_fp16.h>

// ---------------- problem constants ----------------
#define NN   50000
#define EE   800000
#define ET   (EE + NN)      // edges + self loops = 850000
#define HC   256            // HEADS * 64
#define CC   64
#define NEG  0.2f

// ---------------- device scratch (static, no allocs) ----------------
__device__ __half g_hh [(size_t)NN * HC];  // hidden, fp16, [N,256]
__device__ float  g_as [NN * 4];           // alpha_src [N,H]
__device__ float  g_ad [NN * 4];           // alpha_dst [N,H]
__device__ float  g_w  [(size_t)ET * 4];   // per-edge exp values (CSR order)
__device__ float  g_x2 [(size_t)NN * CC];  // layer1 output (fp32)
__device__ int    g_srcs[ET];              // CSR: src per edge, grouped by dst
__device__ int    g_cnt[NN];
__device__ int    g_cur[NN];
__device__ int    g_off[NN];
__device__ int    g_total;
__device__ int    g_is64;

// ---------------- helpers ----------------
__device__ __forceinline__ void edge_sd(const void* ei, int e, int& s, int& d) {
    if (e < EE) {
        if (g_is64) {
            const long long* p = (const long long*)ei;
            s = (int)p[e]; d = (int)p[EE + e];
        } else {
            const int* p = (const int*)ei;
            s = p[e]; d = p[EE + e];
        }
    } else {
        s = d = e - EE;   // self loop
    }
}

__global__ void detect_idx_kernel(const int* __restrict__ words) {
    __shared__ int any;
    if (threadIdx.x == 0) any = 0;
    __syncthreads();
    for (int i = threadIdx.x; i < 1024; i += blockDim.x)
        if (words[2 * i + 1] != 0) any = 1;
    __syncthreads();
    if (threadIdx.x == 0) g_is64 = any ? 0 : 1;
}

// ---------------- CSR build (order-free segments, no scan) ----------------
__global__ void hist_kernel(const void* __restrict__ ei) {
    int e = blockIdx.x * blockDim.x + threadIdx.x;
    if (e >= ET) return;
    int s, d; edge_sd(ei, e, s, d);
    atomicAdd(&g_cnt[d], 1);
}

__global__ void assign_offsets_kernel() {
    int i = blockIdx.x * blockDim.x + threadIdx.x;
    if (i >= NN) return;
    g_off[i] = atomicAdd(&g_total, g_cnt[i]);
}

__global__ void fill_kernel(const void* __restrict__ ei) {
    int e = blockIdx.x * blockDim.x + threadIdx.x;
    if (e >= ET) return;
    int s, d; edge_sd(ei, e, s, d);
    int pos = g_off[d] + atomicAdd(&g_cur[d], 1);
    g_srcs[pos] = s;
}

// ---------------- GEMM + fused alpha epilogue + fp16 store ----------------
__device__ __forceinline__ unsigned long long pack2(float x, float y) {
    unsigned long long r;
    asm("mov.b64 %0, {%1, %2};" : "=l"(r) : "f"(x), "f"(y));
    return r;
}
__device__ __forceinline__ void unpack2(unsigned long long v, float& x, float& y) {
    asm("mov.b64 {%0, %1}, %2;" : "=f"(x), "=f"(y) : "l"(v));
}
__device__ __forceinline__ void ffma2(unsigned long long& acc,
                                      unsigned long long a, unsigned long long b) {
    asm("fma.rn.f32x2 %0, %1, %2, %0;" : "+l"(acc) : "l"(a), "l"(b));
}

template <int K>
__global__ void gemm_nt_kernel(const float* __restrict__ X,
                               const float* __restrict__ W,
                               const float* __restrict__ a_src,
                               const float* __restrict__ a_dst) {
    const int BM = 128, BN = 64, BK = 16;
    __shared__ float Xs[BM * (BK + 1)];
    __shared__ float Wst[BK * (BN + 2)];

    int bm = blockIdx.x * BM, bn = blockIdx.y * BN;   // bn = head*64
    int tid = threadIdx.x;                  // 256 threads
    int tx = tid & 15, ty = tid >> 4;       // micro-tile 8 rows x 4 cols

    unsigned long long acc[8][2];
    #pragma unroll
    for (int i = 0; i < 8; i++) { acc[i][0] = 0ull; acc[i][1] = 0ull; }

    for (int kt = 0; kt < K; kt += BK) {
        #pragma unroll
        for (int l = 0; l < 8; l++) {       // X tile: 128x16
            int lin = tid + l * 256;
            int k = lin & 15, r = lin >> 4;
            int row = bm + r;
            Xs[r * (BK + 1) + k] = (row < NN) ? X[(size_t)row * K + kt + k] : 0.0f;
        }
        #pragma unroll
        for (int l = 0; l < 4; l++) {       // W tile transposed: 16x64
            int lin = tid + l * 256;
            int k = lin & 15, c = lin >> 4;
            Wst[k * (BN + 2) + c] = W[(size_t)(bn + c) * K + kt + k];
        }
        __syncthreads();

        #pragma unroll
        for (int k = 0; k < BK; k++) {
            unsigned long long wp0 = *(const unsigned long long*)&Wst[k * (BN + 2) + tx * 4];
            unsigned long long wp1 = *(const unsigned long long*)&Wst[k * (BN + 2) + tx * 4 + 2];
            #pragma unroll
            for (int i = 0; i < 8; i++) {
                float x = Xs[(ty * 8 + i) * (BK + 1) + k];
                unsigned long long xp = pack2(x, x);
                ffma2(acc[i][0], xp, wp0);
                ffma2(acc[i][1], xp, wp1);
            }
        }
        __syncthreads();
    }

    // ---- epilogue: fp16 store + alpha dot products ----
    float4 asv = *(const float4*)&a_src[bn + tx * 4];
    float4 adv = *(const float4*)&a_dst[bn + tx * 4];
    int head = bn >> 6;

    #pragma unroll
    for (int i = 0; i < 8; i++) {
        int row = bm + ty * 8 + i;
        float f0, f1, f2, f3;
        unpack2(acc[i][0], f0, f1);
        unpack2(acc[i][1], f2, f3);

        if (row < NN) {
            __half2 p0 = __floats2half2_rn(f0, f1);
            __half2 p1 = __floats2half2_rn(f2, f3);
            uint2 u;
            u.x = *(unsigned*)&p0; u.y = *(unsigned*)&p1;
            *(uint2*)&g_hh[(size_t)row * HC + bn + tx * 4] = u;
        }

        float s = f0 * asv.x + f1 * asv.y + f2 * asv.z + f3 * asv.w;
        float d = f0 * adv.x + f1 * adv.y + f2 * adv.z + f3 * adv.w;
        #pragma unroll
        for (int o = 8; o > 0; o >>= 1) {   // reduce over 16 tx lanes
            s += __shfl_xor_sync(0xFFFFFFFFu, s, o);
            d += __shfl_xor_sync(0xFFFFFFFFu, d, o);
        }
        if (tx == 0 && row < NN) {
            g_as[row * 4 + head] = s;
            g_ad[row * 4 + head] = d;
        }
    }
}

// ------- fused softmax (no max) + aggregate: one warp per destination ------
__device__ __forceinline__ void gather_edge(int s, float wa, float wb, int lane,
                                            float& a0, float& a1, float& a2, float& a3) {
    const __half2* hp = (const __half2*)(g_hh + (size_t)s * HC);
    uint2 ua = *(const uint2*)&hp[lane * 2];        // heads 0|1, 8B
    uint2 ub = *(const uint2*)&hp[64 + lane * 2];   // heads 2|3, 8B
    float2 fa0 = __half22float2(*(const __half2*)&ua.x);
    float2 fa1 = __half22float2(*(const __half2*)&ua.y);
    float2 fb0 = __half22float2(*(const __half2*)&ub.x);
    float2 fb1 = __half22float2(*(const __half2*)&ub.y);
    a0 += fa0.x * wa + fb0.x * wb;
    a1 += fa0.y * wa + fb0.y * wb;
    a2 += fa1.x * wa + fb1.x * wb;
    a3 += fa1.y * wa + fb1.y * wb;
}

template <int ACT>
__global__ void aggregate_kernel(float* __restrict__ out,
                                 const float* __restrict__ bias) {
    int d = (blockIdx.x * blockDim.x + threadIdx.x) >> 5;
    int lane = threadIdx.x & 31;
    if (d >= NN) return;
    int beg = g_off[d], end = beg + g_cnt[d];
    float4 ad = *(const float4*)(g_ad + d * 4);

    // ---- pass 1: exp + denom (lane-strided) ----
    float d0 = 0.f, d1 = 0.f, d2 = 0.f, d3 = 0.f;
    for (int i = beg + lane; i < end; i += 32) {
        int s = g_srcs[i];
        float4 as = *(const float4*)(g_as + s * 4);
        float e0 = as.x + ad.x; e0 = e0 > 0.f ? e0 : NEG * e0; e0 = __expf(e0);
        float e1 = as.y + ad.y; e1 = e1 > 0.f ? e1 : NEG * e1; e1 = __expf(e1);
        float e2 = as.z + ad.z; e2 = e2 > 0.f ? e2 : NEG * e2; e2 = __expf(e2);
        float e3 = as.w + ad.w; e3 = e3 > 0.f ? e3 : NEG * e3; e3 = __expf(e3);
        *(float4*)(g_w + (size_t)i * 4) = make_float4(e0, e1, e2, e3);
        d0 += e0; d1 += e1; d2 += e2; d3 += e3;
    }
    #pragma unroll
    for (int o = 16; o > 0; o >>= 1) {
        d0 += __shfl_xor_sync(0xFFFFFFFFu, d0, o);
        d1 += __shfl_xor_sync(0xFFFFFFFFu, d1, o);
        d2 += __shfl_xor_sync(0xFFFFFFFFu, d2, o);
        d3 += __shfl_xor_sync(0xFFFFFFFFu, d3, o);
    }
    float i0 = 0.25f / (d0 + 1e-16f);
    float i1 = 0.25f / (d1 + 1e-16f);
    float i2 = 0.25f / (d2 + 1e-16f);
    float i3 = 0.25f / (d3 + 1e-16f);
    __syncwarp();   // g_w stores visible within warp

    // ---- pass 2: weighted gather-accumulate, unrolled x2 for MLP ----
    bool hi = lane >= 16;
    float acc0 = 0.f, acc1 = 0.f, acc2 = 0.f, acc3 = 0.f;
    int i = beg;
    for (; i + 1 < end; i += 2) {
        int s0 = g_srcs[i], s1 = g_srcs[i + 1];
        float4 w0 = *(const float4*)(g_w + (size_t)i * 4);
        float4 w1 = *(const float4*)(g_w + (size_t)(i + 1) * 4);
        float wa0 = hi ? w0.y * i1 : w0.x * i0;
        float wb0 = hi ? w0.w * i3 : w0.z * i2;
        float wa1 = hi ? w1.y * i1 : w1.x * i0;
        float wb1 = hi ? w1.w * i3 : w1.z * i2;
        gather_edge(s0, wa0, wb0, lane, acc0, acc1, acc2, acc3);
        gather_edge(s1, wa1, wb1, lane, acc0, acc1, acc2, acc3);
    }
    if (i < end) {
        int s0 = g_srcs[i];
        float4 w0 = *(const float4*)(g_w + (size_t)i * 4);
        float wa0 = hi ? w0.y * i1 : w0.x * i0;
        float wb0 = hi ? w0.w * i3 : w0.z * i2;
        gather_edge(s0, wa0, wb0, lane, acc0, acc1, acc2, acc3);
    }
    // combine head pairs: lanes 0-15 += lanes 16-31 (same cols)
    acc0 += __shfl_down_sync(0xFFFFFFFFu, acc0, 16);
    acc1 += __shfl_down_sync(0xFFFFFFFFu, acc1, 16);
    acc2 += __shfl_down_sync(0xFFFFFFFFu, acc2, 16);
    acc3 += __shfl_down_sync(0xFFFFFFFFu, acc3, 16);

    if (lane < 16) {
        float4 bv = *(const float4*)(bias + lane * 4);
        float4 r;
        r.x = acc0 + bv.x; r.y = acc1 + bv.y;
        r.z = acc2 + bv.z; r.w = acc3 + bv.w;
        if (ACT) {
            r.x = r.x > 0.f ? r.x : expm1f(r.x);
            r.y = r.y > 0.f ? r.y : expm1f(r.y);
            r.z = r.z > 0.f ? r.z : expm1f(r.z);
            r.w = r.w > 0.f ? r.w : expm1f(r.w);
        }
        *(float4*)(out + (size_t)d * CC + lane * 4) = r;
    }
}

// ---------------- host launch ----------------
extern "C" void kernel_launch(void* const* d_in, const int* in_sizes, int n_in,
                              void* d_out, int out_size) {
    const float* x      = (const float*)d_in[0];
    const void*  ei     = d_in[1];
    const float* W1     = (const float*)d_in[2];
    const float* a_src1 = (const float*)d_in[3];
    const float* a_dst1 = (const float*)d_in[4];
    const float* b1     = (const float*)d_in[5];
    const float* W2     = (const float*)d_in[6];
    const float* a_src2 = (const float*)d_in[7];
    const float* a_dst2 = (const float*)d_in[8];
    const float* b2     = (const float*)d_in[9];
    float* out = (float*)d_out;

    void *p_cnt, *p_cur, *p_tot, *p_x2;
    cudaGetSymbolAddress(&p_cnt, g_cnt);
    cudaGetSymbolAddress(&p_cur, g_cur);
    cudaGetSymbolAddress(&p_tot, g_total);
    cudaGetSymbolAddress(&p_x2,  g_x2);

    const int TB = 256;
    dim3 gemm_grid((NN + 127) / 128, HC / 64);
    int warp_blocks = (NN * 32 + TB - 1) / TB;
    int edge_blocks = (ET + TB - 1) / TB;
    int node_blocks = (NN + TB - 1) / TB;

    detect_idx_kernel<<<1, 256>>>((const int*)ei);          // launch 0

    // -------- CSR build (order-free segments) --------
    cudaMemsetAsync(p_cnt, 0, NN * sizeof(int), 0);
    cudaMemsetAsync(p_cur, 0, NN * sizeof(int), 0);
    cudaMemsetAsync(p_tot, 0, sizeof(int), 0);
    hist_kernel<<<edge_blocks, TB>>>(ei);                   // launch 1
    assign_offsets_kernel<<<node_blocks, TB>>>();           // launch 2
    fill_kernel<<<edge_blocks, TB>>>(ei);                   // launch 3

    // -------- layer 1 --------
    gemm_nt_kernel<128><<<gemm_grid, TB>>>(x, W1, a_src1, a_dst1);  // launch 4
    aggregate_kernel<1><<<warp_blocks, TB>>>((float*)p_x2, b1);     // launch 5 (ncu lands here)

    // -------- layer 2 --------
    gemm_nt_kernel<64><<<gemm_grid, TB>>>((const float*)p_x2, W2, a_src2, a_dst2);
    aggregate_kernel<0><<<warp_blocks, TB>>>(out, b2);
}

// round 5
// speedup vs baseline: 1.9309x; 1.0532x over previous
#include <cuda_runtime.h>
#include <cuda_fp16.h>

// ---------------- problem constants ----------------
#define NN   50000
#define EE   800000
#define ET   (EE + NN)      // edges + self loops = 850000
#define HC   256            // HEADS * 64
#define CC   64
#define NEG  0.2f

// ---------------- device scratch (static, no allocs) ----------------
__device__ __half g_hh [(size_t)NN * HC];  // hidden, fp16, [N,256]
__device__ float  g_as [NN * 4];           // alpha_src [N,H]
__device__ float  g_ad [NN * 4];           // alpha_dst [N,H]
__device__ float  g_w  [(size_t)ET * 4];   // per-edge exp values (CSR order)
__device__ float  g_x2 [(size_t)NN * CC];  // layer1 output (fp32)
__device__ int    g_srcs[ET];              // CSR: src per edge, grouped by dst
__device__ int    g_cnt[NN];
__device__ int    g_cur[NN];
__device__ int    g_off[NN];
__device__ int    g_total;
__device__ int    g_is64;

// ---------------- helpers ----------------
__device__ __forceinline__ void edge_sd(const void* ei, int e, int& s, int& d) {
    if (e < EE) {
        if (g_is64) {
            const long long* p = (const long long*)ei;
            s = (int)p[e]; d = (int)p[EE + e];
        } else {
            const int* p = (const int*)ei;
            s = p[e]; d = p[EE + e];
        }
    } else {
        s = d = e - EE;   // self loop
    }
}

// ---------------- fused init: zero counters + dtype detection ----------------
__global__ void init_kernel(const int* __restrict__ words) {
    int i = blockIdx.x * blockDim.x + threadIdx.x;
    if (i < NN) { g_cnt[i] = 0; g_cur[i] = 0; }
    if (blockIdx.x == 0) {
        __shared__ int any;
        if (threadIdx.x == 0) { any = 0; g_total = 0; }
        __syncthreads();
        for (int j = threadIdx.x; j < 1024; j += blockDim.x)
            if (words[2 * j + 1] != 0) any = 1;
        __syncthreads();
        if (threadIdx.x == 0) g_is64 = any ? 0 : 1;
    }
}

// ---------------- CSR build (order-free segments, no scan) ----------------
__global__ void hist_kernel(const void* __restrict__ ei) {
    int e = blockIdx.x * blockDim.x + threadIdx.x;
    if (e >= ET) return;
    int s, d; edge_sd(ei, e, s, d);
    atomicAdd(&g_cnt[d], 1);
}

__global__ void assign_offsets_kernel() {
    int i = blockIdx.x * blockDim.x + threadIdx.x;
    if (i >= NN) return;
    g_off[i] = atomicAdd(&g_total, g_cnt[i]);
}

__global__ void fill_kernel(const void* __restrict__ ei) {
    int e = blockIdx.x * blockDim.x + threadIdx.x;
    if (e >= ET) return;
    int s, d; edge_sd(ei, e, s, d);
    int pos = g_off[d] + atomicAdd(&g_cur[d], 1);
    g_srcs[pos] = s;
}

// ---------------- GEMM + fused alpha epilogue + fp16 store ----------------
__device__ __forceinline__ unsigned long long pack2(float x, float y) {
    unsigned long long r;
    asm("mov.b64 %0, {%1, %2};" : "=l"(r) : "f"(x), "f"(y));
    return r;
}
__device__ __forceinline__ void unpack2(unsigned long long v, float& x, float& y) {
    asm("mov.b64 {%0, %1}, %2;" : "=f"(x), "=f"(y) : "l"(v));
}
__device__ __forceinline__ void ffma2(unsigned long long& acc,
                                      unsigned long long a, unsigned long long b) {
    asm("fma.rn.f32x2 %0, %1, %2, %0;" : "+l"(acc) : "l"(a), "l"(b));
}

template <int K>
__global__ void gemm_nt_kernel(const float* __restrict__ X,
                               const float* __restrict__ W,
                               const float* __restrict__ a_src,
                               const float* __restrict__ a_dst) {
    const int BM = 128, BN = 64, BK = 16;
    __shared__ float Xs[BM * (BK + 1)];
    __shared__ float Wst[BK * (BN + 2)];

    int bm = blockIdx.x * BM, bn = blockIdx.y * BN;   // bn = head*64
    int tid = threadIdx.x;                  // 256 threads
    int tx = tid & 15, ty = tid >> 4;       // micro-tile 8 rows x 4 cols

    unsigned long long acc[8][2];
    #pragma unroll
    for (int i = 0; i < 8; i++) { acc[i][0] = 0ull; acc[i][1] = 0ull; }

    for (int kt = 0; kt < K; kt += BK) {
        #pragma unroll
        for (int l = 0; l < 8; l++) {       // X tile: 128x16
            int lin = tid + l * 256;
            int k = lin & 15, r = lin >> 4;
            int row = bm + r;
            Xs[r * (BK + 1) + k] = (row < NN) ? X[(size_t)row * K + kt + k] : 0.0f;
        }
        #pragma unroll
        for (int l = 0; l < 4; l++) {       // W tile transposed: 16x64
            int lin = tid + l * 256;
            int k = lin & 15, c = lin >> 4;
            Wst[k * (BN + 2) + c] = W[(size_t)(bn + c) * K + kt + k];
        }
        __syncthreads();

        #pragma unroll
        for (int k = 0; k < BK; k++) {
            unsigned long long wp0 = *(const unsigned long long*)&Wst[k * (BN + 2) + tx * 4];
            unsigned long long wp1 = *(const unsigned long long*)&Wst[k * (BN + 2) + tx * 4 + 2];
            #pragma unroll
            for (int i = 0; i < 8; i++) {
                float x = Xs[(ty * 8 + i) * (BK + 1) + k];
                unsigned long long xp = pack2(x, x);
                ffma2(acc[i][0], xp, wp0);
                ffma2(acc[i][1], xp, wp1);
            }
        }
        __syncthreads();
    }

    // ---- epilogue: fp16 store + alpha dot products ----
    float4 asv = *(const float4*)&a_src[bn + tx * 4];
    float4 adv = *(const float4*)&a_dst[bn + tx * 4];
    int head = bn >> 6;

    #pragma unroll
    for (int i = 0; i < 8; i++) {
        int row = bm + ty * 8 + i;
        float f0, f1, f2, f3;
        unpack2(acc[i][0], f0, f1);
        unpack2(acc[i][1], f2, f3);

        if (row < NN) {
            __half2 p0 = __floats2half2_rn(f0, f1);
            __half2 p1 = __floats2half2_rn(f2, f3);
            uint2 u;
            u.x = *(unsigned*)&p0; u.y = *(unsigned*)&p1;
            *(uint2*)&g_hh[(size_t)row * HC + bn + tx * 4] = u;
        }

        float s = f0 * asv.x + f1 * asv.y + f2 * asv.z + f3 * asv.w;
        float d = f0 * adv.x + f1 * adv.y + f2 * adv.z + f3 * adv.w;
        #pragma unroll
        for (int o = 8; o > 0; o >>= 1) {   // reduce over 16 tx lanes
            s += __shfl_xor_sync(0xFFFFFFFFu, s, o);
            d += __shfl_xor_sync(0xFFFFFFFFu, d, o);
        }
        if (tx == 0 && row < NN) {
            g_as[row * 4 + head] = s;
            g_ad[row * 4 + head] = d;
        }
    }
}

// ------- fused softmax (no max) + aggregate: one warp per destination ------
template <int ACT>
__global__ void __launch_bounds__(256)
aggregate_kernel(float* __restrict__ out, const float* __restrict__ bias) {
    int d = (blockIdx.x * blockDim.x + threadIdx.x) >> 5;
    int lane = threadIdx.x & 31;
    if (d >= NN) return;
    int beg = g_off[d], end = beg + g_cnt[d];
    float4 ad = *(const float4*)(g_ad + d * 4);

    // ---- pass 1: exp + denom (lane-strided) ----
    float d0 = 0.f, d1 = 0.f, d2 = 0.f, d3 = 0.f;
    for (int i = beg + lane; i < end; i += 32) {
        int s = g_srcs[i];
        float4 as = *(const float4*)(g_as + s * 4);
        float e0 = as.x + ad.x; e0 = e0 > 0.f ? e0 : NEG * e0; e0 = __expf(e0);
        float e1 = as.y + ad.y; e1 = e1 > 0.f ? e1 : NEG * e1; e1 = __expf(e1);
        float e2 = as.z + ad.z; e2 = e2 > 0.f ? e2 : NEG * e2; e2 = __expf(e2);
        float e3 = as.w + ad.w; e3 = e3 > 0.f ? e3 : NEG * e3; e3 = __expf(e3);
        *(float4*)(g_w + (size_t)i * 4) = make_float4(e0, e1, e2, e3);
        d0 += e0; d1 += e1; d2 += e2; d3 += e3;
    }
    #pragma unroll
    for (int o = 16; o > 0; o >>= 1) {
        d0 += __shfl_xor_sync(0xFFFFFFFFu, d0, o);
        d1 += __shfl_xor_sync(0xFFFFFFFFu, d1, o);
        d2 += __shfl_xor_sync(0xFFFFFFFFu, d2, o);
        d3 += __shfl_xor_sync(0xFFFFFFFFu, d3, o);
    }
    float i0 = 0.25f / (d0 + 1e-16f);
    float i1 = 0.25f / (d1 + 1e-16f);
    float i2 = 0.25f / (d2 + 1e-16f);
    float i3 = 0.25f / (d3 + 1e-16f);
    __syncwarp();   // g_w stores visible within warp

    // ---- pass 2: weighted gather-accumulate, unroll x4, loads first ----
    bool hi = lane >= 16;
    float acc0 = 0.f, acc1 = 0.f, acc2 = 0.f, acc3 = 0.f;
    int i = beg;
    for (; i + 3 < end; i += 4) {
        int s[4];
        float4 w[4];
        uint2 ua[4], ub[4];
        #pragma unroll
        for (int j = 0; j < 4; j++) s[j] = g_srcs[i + j];
        #pragma unroll
        for (int j = 0; j < 4; j++) w[j] = *(const float4*)(g_w + (size_t)(i + j) * 4);
        #pragma unroll
        for (int j = 0; j < 4; j++) {
            const __half2* hp = (const __half2*)(g_hh + (size_t)s[j] * HC);
            ua[j] = *(const uint2*)&hp[lane * 2];        // heads 0|1
            ub[j] = *(const uint2*)&hp[64 + lane * 2];   // heads 2|3
        }
        #pragma unroll
        for (int j = 0; j < 4; j++) {
            float wa = hi ? w[j].y * i1 : w[j].x * i0;
            float wb = hi ? w[j].w * i3 : w[j].z * i2;
            float2 fa0 = __half22float2(*(const __half2*)&ua[j].x);
            float2 fa1 = __half22float2(*(const __half2*)&ua[j].y);
            float2 fb0 = __half22float2(*(const __half2*)&ub[j].x);
            float2 fb1 = __half22float2(*(const __half2*)&ub[j].y);
            acc0 += fa0.x * wa + fb0.x * wb;
            acc1 += fa0.y * wa + fb0.y * wb;
            acc2 += fa1.x * wa + fb1.x * wb;
            acc3 += fa1.y * wa + fb1.y * wb;
        }
    }
    for (; i < end; i++) {
        int s0 = g_srcs[i];
        float4 w0 = *(const float4*)(g_w + (size_t)i * 4);
        float wa = hi ? w0.y * i1 : w0.x * i0;
        float wb = hi ? w0.w * i3 : w0.z * i2;
        const __half2* hp = (const __half2*)(g_hh + (size_t)s0 * HC);
        uint2 ua = *(const uint2*)&hp[lane * 2];
        uint2 ub = *(const uint2*)&hp[64 + lane * 2];
        float2 fa0 = __half22float2(*(const __half2*)&ua.x);
        float2 fa1 = __half22float2(*(const __half2*)&ua.y);
        float2 fb0 = __half22float2(*(const __half2*)&ub.x);
        float2 fb1 = __half22float2(*(const __half2*)&ub.y);
        acc0 += fa0.x * wa + fb0.x * wb;
        acc1 += fa0.y * wa + fb0.y * wb;
        acc2 += fa1.x * wa + fb1.x * wb;
        acc3 += fa1.y * wa + fb1.y * wb;
    }
    // combine head pairs: lanes 0-15 += lanes 16-31 (same cols)
    acc0 += __shfl_down_sync(0xFFFFFFFFu, acc0, 16);
    acc1 += __shfl_down_sync(0xFFFFFFFFu, acc1, 16);
    acc2 += __shfl_down_sync(0xFFFFFFFFu, acc2, 16);
    acc3 += __shfl_down_sync(0xFFFFFFFFu, acc3, 16);

    if (lane < 16) {
        float4 bv = *(const float4*)(bias + lane * 4);
        float4 r;
        r.x = acc0 + bv.x; r.y = acc1 + bv.y;
        r.z = acc2 + bv.z; r.w = acc3 + bv.w;
        if (ACT) {
            r.x = r.x > 0.f ? r.x : expm1f(r.x);
            r.y = r.y > 0.f ? r.y : expm1f(r.y);
            r.z = r.z > 0.f ? r.z : expm1f(r.z);
            r.w = r.w > 0.f ? r.w : expm1f(r.w);
        }
        *(float4*)(out + (size_t)d * CC + lane * 4) = r;
    }
}

// ---------------- host launch ----------------
extern "C" void kernel_launch(void* const* d_in, const int* in_sizes, int n_in,
                              void* d_out, int out_size) {
    const float* x      = (const float*)d_in[0];
    const void*  ei     = d_in[1];
    const float* W1     = (const float*)d_in[2];
    const float* a_src1 = (const float*)d_in[3];
    const float* a_dst1 = (const float*)d_in[4];
    const float* b1     = (const float*)d_in[5];
    const float* W2     = (const float*)d_in[6];
    const float* a_src2 = (const float*)d_in[7];
    const float* a_dst2 = (const float*)d_in[8];
    const float* b2     = (const float*)d_in[9];
    float* out = (float*)d_out;

    void* p_x2;
    cudaGetSymbolAddress(&p_x2, g_x2);

    // lazily-created side stream + fork/join events (host objects, one-time)
    static cudaStream_t s2 = []{
        cudaStream_t t; cudaStreamCreateWithFlags(&t, cudaStreamNonBlocking); return t;
    }();
    static cudaEvent_t ev_fork = []{
        cudaEvent_t e; cudaEventCreateWithFlags(&e, cudaEventDisableTiming); return e;
    }();
    static cudaEvent_t ev_join = []{
        cudaEvent_t e; cudaEventCreateWithFlags(&e, cudaEventDisableTiming); return e;
    }();

    const int TB = 256;
    dim3 gemm_grid((NN + 127) / 128, HC / 64);
    int warp_blocks = (NN * 32 + TB - 1) / TB;
    int edge_blocks = (ET + TB - 1) / TB;
    int node_blocks = (NN + TB - 1) / TB;

    // -------- fork: CSR build on side stream, GEMM1 on main stream --------
    cudaEventRecord(ev_fork, 0);
    cudaStreamWaitEvent(s2, ev_fork, 0);

    init_kernel<<<node_blocks, TB, 0, s2>>>((const int*)ei);
    hist_kernel<<<edge_blocks, TB, 0, s2>>>(ei);
    assign_offsets_kernel<<<node_blocks, TB, 0, s2>>>();
    fill_kernel<<<edge_blocks, TB, 0, s2>>>(ei);
    cudaEventRecord(ev_join, s2);

    gemm_nt_kernel<128><<<gemm_grid, TB>>>(x, W1, a_src1, a_dst1);

    // -------- join, then the serial tail --------
    cudaStreamWaitEvent(0, ev_join, 0);
    aggregate_kernel<1><<<warp_blocks, TB>>>((float*)p_x2, b1);
    gemm_nt_kernel<64><<<gemm_grid, TB>>>((const float*)p_x2, W2, a_src2, a_dst2);
    aggregate_kernel<0><<<warp_blocks, TB>>>(out, b2);
}

// round 6
// speedup vs baseline: 1.9524x; 1.0112x over previous
#include <cuda_runtime.h>
#include <cuda_fp16.h>

// ---------------- problem constants ----------------
#define NN    50000
#define EE    800000
#define ET    (EE + NN)      // edges + self loops = 850000
#define HC    256            // HEADS * 64
#define CC    64
#define NEG   0.2f
#define SPLIT 25088          // pipeline split point (multiple of 128)

// ---------------- device scratch (static, no allocs) ----------------
__device__ __half g_hh [(size_t)NN * HC];  // hidden, fp16, [N,256]
__device__ float  g_as [NN * 4];           // alpha_src [N,H]
__device__ float  g_ad [NN * 4];           // alpha_dst [N,H]
__device__ float  g_w  [(size_t)ET * 4];   // per-edge exp values (CSR order)
__device__ float  g_x2 [(size_t)NN * CC];  // layer1 output (fp32)
__device__ int    g_srcs[ET];              // CSR: src per edge, grouped by dst
__device__ int    g_cnt[NN];
__device__ int    g_cur[NN];
__device__ int    g_off[NN];
__device__ int    g_total;
__device__ int    g_is64;

typedef unsigned long long ull;

// ---------------- helpers ----------------
__device__ __forceinline__ void edge_sd(const void* ei, int e, int& s, int& d) {
    if (e < EE) {
        if (g_is64) {
            const long long* p = (const long long*)ei;
            s = (int)p[e]; d = (int)p[EE + e];
        } else {
            const int* p = (const int*)ei;
            s = p[e]; d = p[EE + e];
        }
    } else {
        s = d = e - EE;   // self loop
    }
}

// ---------------- fused init: zero counters + dtype detection ----------------
__global__ void init_kernel(const int* __restrict__ words) {
    int i = blockIdx.x * blockDim.x + threadIdx.x;
    if (i < NN) { g_cnt[i] = 0; g_cur[i] = 0; }
    if (blockIdx.x == 0) {
        __shared__ int any;
        if (threadIdx.x == 0) { any = 0; g_total = 0; }
        __syncthreads();
        for (int j = threadIdx.x; j < 1024; j += blockDim.x)
            if (words[2 * j + 1] != 0) any = 1;
        __syncthreads();
        if (threadIdx.x == 0) g_is64 = any ? 0 : 1;
    }
}

// ---------------- CSR build ----------------
__global__ void hist_kernel(const void* __restrict__ ei) {
    int e = blockIdx.x * blockDim.x + threadIdx.x;
    if (e >= ET) return;
    int d;
    if (e < EE) {
        // dst only: low 32-bit word suffices (indices < N)
        d = g_is64 ? ((const int*)ei)[2 * (EE + e)] : ((const int*)ei)[EE + e];
    } else {
        d = e - EE;
    }
    atomicAdd(&g_cnt[d], 1);
}

__global__ void assign_offsets_kernel() {
    int i = blockIdx.x * blockDim.x + threadIdx.x;
    if (i >= NN) return;
    g_off[i] = atomicAdd(&g_total, g_cnt[i]);
}

__global__ void fill_kernel(const void* __restrict__ ei) {
    int e = blockIdx.x * blockDim.x + threadIdx.x;
    if (e >= ET) return;
    int s, d; edge_sd(ei, e, s, d);
    int pos = g_off[d] + atomicAdd(&g_cur[d], 1);
    g_srcs[pos] = s;
}

// ---------------- GEMM + fused alpha epilogue + fp16 store ----------------
__device__ __forceinline__ void ffma2(ull& acc, ull a, ull b) {
    asm("fma.rn.f32x2 %0, %1, %2, %0;" : "+l"(acc) : "l"(a), "l"(b));
}
__device__ __forceinline__ void unpack2(ull v, float& x, float& y) {
    asm("mov.b64 {%0, %1}, %2;" : "=f"(x), "=f"(y) : "l"(v));
}

template <int K>
__global__ void gemm_nt_kernel(const float* __restrict__ X,
                               const float* __restrict__ W,
                               const float* __restrict__ a_src,
                               const float* __restrict__ a_dst,
                               int row0) {
    const int BM = 128, BN = 64, BK = 16;
    __shared__ float2 Xs2[BM * BK];          // duplicated (x,x)
    __shared__ float  Wst[BK * (BN + 4)];    // [k][c], pad 68 keeps 16B align

    int bm = row0 + blockIdx.x * BM, bn = blockIdx.y * BN;  // bn = head*64
    int tid = threadIdx.x;                   // 256 threads
    int tx = tid & 15, ty = tid >> 4;        // micro-tile 8 rows x 4 cols

    ull acc[8][2];
    #pragma unroll
    for (int i = 0; i < 8; i++) { acc[i][0] = 0ull; acc[i][1] = 0ull; }

    for (int kt = 0; kt < K; kt += BK) {
        #pragma unroll
        for (int l = 0; l < 8; l++) {        // X tile: 128x16 duplicated
            int lin = tid + l * 256;
            int k = lin & 15, r = lin >> 4;
            int row = bm + r;
            float v = (row < NN) ? X[(size_t)row * K + kt + k] : 0.0f;
            Xs2[r * BK + k] = make_float2(v, v);
        }
        #pragma unroll
        for (int l = 0; l < 4; l++) {        // W tile transposed: 16x64
            int lin = tid + l * 256;
            int k = lin & 15, c = lin >> 4;
            Wst[k * (BN + 4) + c] = W[(size_t)(bn + c) * K + kt + k];
        }
        __syncthreads();

        #pragma unroll
        for (int k = 0; k < BK; k++) {
            ulonglong2 wp = *(const ulonglong2*)&Wst[k * (BN + 4) + tx * 4];
            #pragma unroll
            for (int i = 0; i < 8; i++) {
                float2 xv = Xs2[(ty * 8 + i) * BK + k];
                ull xp = *(ull*)&xv;
                ffma2(acc[i][0], xp, wp.x);
                ffma2(acc[i][1], xp, wp.y);
            }
        }
        __syncthreads();
    }

    // ---- epilogue: fp16 store + alpha dot products ----
    float4 asv = *(const float4*)&a_src[bn + tx * 4];
    float4 adv = *(const float4*)&a_dst[bn + tx * 4];
    int head = bn >> 6;

    #pragma unroll
    for (int i = 0; i < 8; i++) {
        int row = bm + ty * 8 + i;
        float f0, f1, f2, f3;
        unpack2(acc[i][0], f0, f1);
        unpack2(acc[i][1], f2, f3);

        if (row < NN) {
            __half2 p0 = __floats2half2_rn(f0, f1);
            __half2 p1 = __floats2half2_rn(f2, f3);
            uint2 u;
            u.x = *(unsigned*)&p0; u.y = *(unsigned*)&p1;
            *(uint2*)&g_hh[(size_t)row * HC + bn + tx * 4] = u;
        }

        float s = f0 * asv.x + f1 * asv.y + f2 * asv.z + f3 * asv.w;
        float d = f0 * adv.x + f1 * adv.y + f2 * adv.z + f3 * adv.w;
        #pragma unroll
        for (int o = 8; o > 0; o >>= 1) {    // reduce over 16 tx lanes
            s += __shfl_xor_sync(0xFFFFFFFFu, s, o);
            d += __shfl_xor_sync(0xFFFFFFFFu, d, o);
        }
        if (tx == 0 && row < NN) {
            g_as[row * 4 + head] = s;
            g_ad[row * 4 + head] = d;
        }
    }
}

// ------- fused softmax (no max) + aggregate: one warp per destination ------
// pass 2: lane L loads 16B of the 512B fp16 row (head = L>>3, colgrp = L&7)
template <int ACT>
__global__ void __launch_bounds__(256)
aggregate_kernel(float* __restrict__ out, const float* __restrict__ bias,
                 int d0, int nd) {
    int d = d0 + ((blockIdx.x * blockDim.x + threadIdx.x) >> 5);
    int lane = threadIdx.x & 31;
    if (d >= d0 + nd) return;
    int beg = g_off[d], end = beg + g_cnt[d];
    float4 ad = *(const float4*)(g_ad + d * 4);

    // ---- pass 1: exp + denom (lane-strided) ----
    float d0s = 0.f, d1s = 0.f, d2s = 0.f, d3s = 0.f;
    for (int i = beg + lane; i < end; i += 32) {
        int s = g_srcs[i];
        float4 as = *(const float4*)(g_as + s * 4);
        float e0 = as.x + ad.x; e0 = e0 > 0.f ? e0 : NEG * e0; e0 = __expf(e0);
        float e1 = as.y + ad.y; e1 = e1 > 0.f ? e1 : NEG * e1; e1 = __expf(e1);
        float e2 = as.z + ad.z; e2 = e2 > 0.f ? e2 : NEG * e2; e2 = __expf(e2);
        float e3 = as.w + ad.w; e3 = e3 > 0.f ? e3 : NEG * e3; e3 = __expf(e3);
        *(float4*)(g_w + (size_t)i * 4) = make_float4(e0, e1, e2, e3);
        d0s += e0; d1s += e1; d2s += e2; d3s += e3;
    }
    #pragma unroll
    for (int o = 16; o > 0; o >>= 1) {
        d0s += __shfl_xor_sync(0xFFFFFFFFu, d0s, o);
        d1s += __shfl_xor_sync(0xFFFFFFFFu, d1s, o);
        d2s += __shfl_xor_sync(0xFFFFFFFFu, d2s, o);
        d3s += __shfl_xor_sync(0xFFFFFFFFu, d3s, o);
    }
    float i0 = 0.25f / (d0s + 1e-16f);
    float i1 = 0.25f / (d1s + 1e-16f);
    float i2 = 0.25f / (d2s + 1e-16f);
    float i3 = 0.25f / (d3s + 1e-16f);
    __syncwarp();

    // ---- pass 2: full-row LDG.128 gather, head via lane select ----
    int hsel = lane >> 3;                    // 0..3
    float acc[8];
    #pragma unroll
    for (int k = 0; k < 8; k++) acc[k] = 0.f;

    int i = beg;
    for (; i + 3 < end; i += 4) {
        int   s[4];
        float4 w[4];
        uint4 u[4];
        #pragma unroll
        for (int j = 0; j < 4; j++) s[j] = g_srcs[i + j];
        #pragma unroll
        for (int j = 0; j < 4; j++) w[j] = *(const float4*)(g_w + (size_t)(i + j) * 4);
        #pragma unroll
        for (int j = 0; j < 4; j++)
            u[j] = ((const uint4*)(g_hh + (size_t)s[j] * HC))[lane];
        #pragma unroll
        for (int j = 0; j < 4; j++) {
            float wh = hsel == 0 ? w[j].x * i0 :
                       hsel == 1 ? w[j].y * i1 :
                       hsel == 2 ? w[j].z * i2 : w[j].w * i3;
            float2 f0 = __half22float2(*(const __half2*)&u[j].x);
            float2 f1 = __half22float2(*(const __half2*)&u[j].y);
            float2 f2 = __half22float2(*(const __half2*)&u[j].z);
            float2 f3 = __half22float2(*(const __half2*)&u[j].w);
            acc[0] += f0.x * wh; acc[1] += f0.y * wh;
            acc[2] += f1.x * wh; acc[3] += f1.y * wh;
            acc[4] += f2.x * wh; acc[5] += f2.y * wh;
            acc[6] += f3.x * wh; acc[7] += f3.y * wh;
        }
    }
    for (; i < end; i++) {
        int s0 = g_srcs[i];
        float4 w0 = *(const float4*)(g_w + (size_t)i * 4);
        uint4 u0 = ((const uint4*)(g_hh + (size_t)s0 * HC))[lane];
        float wh = hsel == 0 ? w0.x * i0 :
                   hsel == 1 ? w0.y * i1 :
                   hsel == 2 ? w0.z * i2 : w0.w * i3;
        float2 f0 = __half22float2(*(const __half2*)&u0.x);
        float2 f1 = __half22float2(*(const __half2*)&u0.y);
        float2 f2 = __half22float2(*(const __half2*)&u0.z);
        float2 f3 = __half22float2(*(const __half2*)&u0.w);
        acc[0] += f0.x * wh; acc[1] += f0.y * wh;
        acc[2] += f1.x * wh; acc[3] += f1.y * wh;
        acc[4] += f2.x * wh; acc[5] += f2.y * wh;
        acc[6] += f3.x * wh; acc[7] += f3.y * wh;
    }

    // head-sum: lanes with same (lane&7) hold the 4 heads of one col group
    #pragma unroll
    for (int k = 0; k < 8; k++) {
        acc[k] += __shfl_xor_sync(0xFFFFFFFFu, acc[k], 8);
        acc[k] += __shfl_xor_sync(0xFFFFFFFFu, acc[k], 16);
    }

    if (lane < 8) {                          // col group = lane, cols lane*8..+7
        float4 b0 = *(const float4*)(bias + lane * 8);
        float4 b1 = *(const float4*)(bias + lane * 8 + 4);
        float4 r0, r1;
        r0.x = acc[0] + b0.x; r0.y = acc[1] + b0.y;
        r0.z = acc[2] + b0.z; r0.w = acc[3] + b0.w;
        r1.x = acc[4] + b1.x; r1.y = acc[5] + b1.y;
        r1.z = acc[6] + b1.z; r1.w = acc[7] + b1.w;
        if (ACT) {
            r0.x = r0.x > 0.f ? r0.x : expm1f(r0.x);
            r0.y = r0.y > 0.f ? r0.y : expm1f(r0.y);
            r0.z = r0.z > 0.f ? r0.z : expm1f(r0.z);
            r0.w = r0.w > 0.f ? r0.w : expm1f(r0.w);
            r1.x = r1.x > 0.f ? r1.x : expm1f(r1.x);
            r1.y = r1.y > 0.f ? r1.y : expm1f(r1.y);
            r1.z = r1.z > 0.f ? r1.z : expm1f(r1.z);
            r1.w = r1.w > 0.f ? r1.w : expm1f(r1.w);
        }
        *(float4*)(out + (size_t)d * CC + lane * 8)     = r0;
        *(float4*)(out + (size_t)d * CC + lane * 8 + 4) = r1;
    }
}

// ---------------- host launch ----------------
extern "C" void kernel_launch(void* const* d_in, const int* in_sizes, int n_in,
                              void* d_out, int out_size) {
    const float* x      = (const float*)d_in[0];
    const void*  ei     = d_in[1];
    const float* W1     = (const float*)d_in[2];
    const float* a_src1 = (const float*)d_in[3];
    const float* a_dst1 = (const float*)d_in[4];
    const float* b1     = (const float*)d_in[5];
    const float* W2     = (const float*)d_in[6];
    const float* a_src2 = (const float*)d_in[7];
    const float* a_dst2 = (const float*)d_in[8];
    const float* b2     = (const float*)d_in[9];
    float* out = (float*)d_out;

    void* p_x2;
    cudaGetSymbolAddress(&p_x2, g_x2);
    float* x2 = (float*)p_x2;

    static cudaStream_t s2 = []{
        cudaStream_t t; cudaStreamCreateWithFlags(&t, cudaStreamNonBlocking); return t;
    }();
    static cudaEvent_t ev_fork = []{
        cudaEvent_t e; cudaEventCreateWithFlags(&e, cudaEventDisableTiming); return e;
    }();
    static cudaEvent_t ev_join = []{
        cudaEvent_t e; cudaEventCreateWithFlags(&e, cudaEventDisableTiming); return e;
    }();
    static cudaEvent_t ev_a0 = []{
        cudaEvent_t e; cudaEventCreateWithFlags(&e, cudaEventDisableTiming); return e;
    }();
    static cudaEvent_t ev_g0 = []{
        cudaEvent_t e; cudaEventCreateWithFlags(&e, cudaEventDisableTiming); return e;
    }();

    const int TB = 256;
    dim3 gemm_full((NN + 127) / 128, HC / 64);
    dim3 gemm_h0(SPLIT / 128, HC / 64);                 // rows [0, SPLIT)
    dim3 gemm_h1((NN - SPLIT + 127) / 128, HC / 64);    // rows [SPLIT, NN)
    int agg_h0 = (SPLIT * 32) / TB;
    int agg_h1 = ((NN - SPLIT) * 32 + TB - 1) / TB;
    int agg_full = (NN * 32 + TB - 1) / TB;
    int edge_blocks = (ET + TB - 1) / TB;
    int node_blocks = (NN + TB - 1) / TB;

    // -------- fork: CSR build on side stream, GEMM1 on main --------
    cudaEventRecord(ev_fork, 0);
    cudaStreamWaitEvent(s2, ev_fork, 0);

    init_kernel<<<node_blocks, TB, 0, s2>>>((const int*)ei);
    hist_kernel<<<edge_blocks, TB, 0, s2>>>(ei);
    assign_offsets_kernel<<<node_blocks, TB, 0, s2>>>();
    fill_kernel<<<edge_blocks, TB, 0, s2>>>(ei);
    cudaEventRecord(ev_join, s2);

    gemm_nt_kernel<128><<<gemm_full, TB>>>(x, W1, a_src1, a_dst1, 0);

    // -------- join; pipelined agg1 / GEMM2 --------
    cudaStreamWaitEvent(0, ev_join, 0);
    aggregate_kernel<1><<<agg_h0, TB>>>(x2, b1, 0, SPLIT);
    cudaEventRecord(ev_a0, 0);
    cudaStreamWaitEvent(s2, ev_a0, 0);
    gemm_nt_kernel<64><<<gemm_h0, TB, 0, s2>>>(x2, W2, a_src2, a_dst2, 0);
    cudaEventRecord(ev_g0, s2);

    aggregate_kernel<1><<<agg_h1, TB>>>(x2, b1, SPLIT, NN - SPLIT);
    gemm_nt_kernel<64><<<gemm_h1, TB>>>(x2, W2, a_src2, a_dst2, SPLIT);

    // -------- final aggregate (needs both GEMM2 halves) --------
    cudaStreamWaitEvent(0, ev_g0, 0);
    aggregate_kernel<0><<<agg_full, TB>>>(out, b2, 0, NN);
}

// round 8
// speedup vs baseline: 2.8908x; 1.4806x over previous
#include <cuda_runtime.h>
#include <cuda_fp16.h>

// ---------------- problem constants ----------------
#define NN    50000
#define EE    800000
#define ET    (EE + NN)      // edges + self loops = 850000
#define HC    256            // HEADS * 64
#define CC    64
#define NEG   0.2f
#define SPLIT 25088          // pipeline split point (multiple of 128)

// ---------------- device scratch (static, no allocs) ----------------
__device__ __half g_hh [(size_t)NN * HC];  // hidden, fp16, [N,256]
__device__ float  g_as [NN * 4];           // alpha_src [N,H]
__device__ float  g_ad [NN * 4];           // alpha_dst [N,H]
__device__ float  g_w  [(size_t)ET * 4];   // per-edge exp values (CSR order)
__device__ float  g_x2 [(size_t)NN * CC];  // layer1 output (fp32)
__device__ int    g_srcs[ET];              // CSR: src per edge, grouped by dst
__device__ int    g_cnt[NN];
__device__ int    g_cur[NN];
__device__ int    g_off[NN];
__device__ int    g_total;
__device__ int    g_is64;

// ---------------- helpers ----------------
__device__ __forceinline__ void edge_sd(const void* ei, int e, int& s, int& d) {
    if (e < EE) {
        if (g_is64) {
            const long long* p = (const long long*)ei;
            s = (int)p[e]; d = (int)p[EE + e];
        } else {
            const int* p = (const int*)ei;
            s = p[e]; d = p[EE + e];
        }
    } else {
        s = d = e - EE;   // self loop
    }
}

// ---------------- fused init: zero counters + dtype detection ----------------
__global__ void init_kernel(const int* __restrict__ words) {
    int i = blockIdx.x * blockDim.x + threadIdx.x;
    if (i < NN) { g_cnt[i] = 0; g_cur[i] = 0; }
    if (blockIdx.x == 0) {
        __shared__ int any;
        if (threadIdx.x == 0) { any = 0; g_total = 0; }
        __syncthreads();
        for (int j = threadIdx.x; j < 1024; j += blockDim.x)
            if (words[2 * j + 1] != 0) any = 1;
        __syncthreads();
        if (threadIdx.x == 0) g_is64 = any ? 0 : 1;
    }
}

// ---------------- CSR build ----------------
__global__ void hist_kernel(const void* __restrict__ ei) {
    int e = blockIdx.x * blockDim.x + threadIdx.x;
    if (e >= ET) return;
    int d;
    if (e < EE) {
        d = g_is64 ? ((const int*)ei)[2 * (EE + e)] : ((const int*)ei)[EE + e];
    } else {
        d = e - EE;
    }
    atomicAdd(&g_cnt[d], 1);
}

__global__ void assign_offsets_kernel() {
    int i = blockIdx.x * blockDim.x + threadIdx.x;
    if (i >= NN) return;
    g_off[i] = atomicAdd(&g_total, g_cnt[i]);
}

__global__ void fill_kernel(const void* __restrict__ ei) {
    int e = blockIdx.x * blockDim.x + threadIdx.x;
    if (e >= ET) return;
    int s, d; edge_sd(ei, e, s, d);
    int pos = g_off[d] + atomicAdd(&g_cur[d], 1);
    g_srcs[pos] = s;
}

// ---------------- tensor-core GEMM (fp16 mma.sync, fp32 accum) ------------
__device__ __forceinline__ unsigned smem_u32(const void* p) {
    return (unsigned)__cvta_generic_to_shared(p);
}
__device__ __forceinline__ void ldmatrix_x4(unsigned& r0, unsigned& r1,
                                            unsigned& r2, unsigned& r3, unsigned addr) {
    asm volatile("ldmatrix.sync.aligned.m8n8.x4.shared.b16 {%0,%1,%2,%3}, [%4];"
                 : "=r"(r0), "=r"(r1), "=r"(r2), "=r"(r3) : "r"(addr));
}
// B stored [n][k] (k contiguous) == col-major kxn: NON-trans x2 yields the
// correct mma B fragment (pairs along k, 8x8 rows = n).
__device__ __forceinline__ void ldmatrix_x2(unsigned& r0, unsigned& r1, unsigned addr) {
    asm volatile("ldmatrix.sync.aligned.m8n8.x2.shared.b16 {%0,%1}, [%2];"
                 : "=r"(r0), "=r"(r1) : "r"(addr));
}
__device__ __forceinline__ void mma16816(float* d, const unsigned* a, const unsigned* b) {
    asm volatile("mma.sync.aligned.m16n8k16.row.col.f32.f16.f16.f32 "
                 "{%0,%1,%2,%3}, {%4,%5,%6,%7}, {%8,%9}, {%0,%1,%2,%3};"
                 : "+f"(d[0]), "+f"(d[1]), "+f"(d[2]), "+f"(d[3])
                 : "r"(a[0]), "r"(a[1]), "r"(a[2]), "r"(a[3]), "r"(b[0]), "r"(b[1]));
}

#define ASTRIDE 40   // halfs per row; 80B row stride -> conflict-free ldmatrix

template <int K>
__global__ void __launch_bounds__(256)
gemm_tc_kernel(const float* __restrict__ X, const float* __restrict__ W,
               const float* __restrict__ a_src, const float* __restrict__ a_dst,
               int row0) {
    __shared__ __align__(16) __half As[128 * ASTRIDE];
    __shared__ __align__(16) __half Bs[64 * ASTRIDE];
    __shared__ float sred[2][128];
    __shared__ float dred[2][128];

    int tid = threadIdx.x;
    int lane = tid & 31, wid = tid >> 5;
    int wm = wid >> 1, wn = wid & 1;         // warp tile: rows wm*32, cols wn*32
    int bm = row0 + blockIdx.x * 128;
    int head = blockIdx.y;
    int bn = head * 64;

    float d[2][4][4];
    #pragma unroll
    for (int mt = 0; mt < 2; mt++)
        #pragma unroll
        for (int nt = 0; nt < 4; nt++)
            #pragma unroll
            for (int j = 0; j < 4; j++) d[mt][nt][j] = 0.f;

    for (int kt = 0; kt < K; kt += 32) {
        // load X tile 128x32 fp32 -> fp16 smem
        #pragma unroll
        for (int i = 0; i < 8; i++) {
            int lin = tid + i * 256;          // 2048 float2
            int r = lin >> 4, c2 = lin & 15;
            int row = bm + r;
            float2 v = make_float2(0.f, 0.f);
            if (row < NN) v = *(const float2*)&X[(size_t)row * K + kt + c2 * 2];
            *(__half2*)&As[r * ASTRIDE + c2 * 2] = __floats2half2_rn(v.x, v.y);
        }
        // load W tile 64x32 fp32 -> fp16 smem
        #pragma unroll
        for (int i = 0; i < 4; i++) {
            int lin = tid + i * 256;          // 1024 float2
            int r = lin >> 4, c2 = lin & 15;
            float2 v = *(const float2*)&W[(size_t)(bn + r) * K + kt + c2 * 2];
            *(__half2*)&Bs[r * ASTRIDE + c2 * 2] = __floats2half2_rn(v.x, v.y);
        }
        __syncthreads();

        #pragma unroll
        for (int kk = 0; kk < 32; kk += 16) {
            unsigned a[2][4], b[4][2];
            int l15 = lane & 15, lh = lane >> 4;
            #pragma unroll
            for (int mt = 0; mt < 2; mt++) {
                unsigned addr = smem_u32(&As[(wm * 32 + mt * 16 + l15) * ASTRIDE + kk + lh * 8]);
                ldmatrix_x4(a[mt][0], a[mt][1], a[mt][2], a[mt][3], addr);
            }
            int l7 = lane & 7, kh = (lane >> 3) & 1;
            #pragma unroll
            for (int nt = 0; nt < 4; nt++) {
                unsigned addr = smem_u32(&Bs[(wn * 32 + nt * 8 + l7) * ASTRIDE + kk + kh * 8]);
                ldmatrix_x2(b[nt][0], b[nt][1], addr);
            }
            #pragma unroll
            for (int mt = 0; mt < 2; mt++)
                #pragma unroll
                for (int nt = 0; nt < 4; nt++)
                    mma16816(d[mt][nt], a[mt], b[nt]);
        }
        __syncthreads();
    }

    // ---- epilogue: fp16 store + alpha partials ----
    int qrow = lane >> 2;                    // 0..7
    int qcol = (lane & 3) * 2;
    float2 av[4], dv[4];
    #pragma unroll
    for (int nt = 0; nt < 4; nt++) {
        int c = wn * 32 + nt * 8 + qcol;
        av[nt] = *(const float2*)&a_src[bn + c];
        dv[nt] = *(const float2*)&a_dst[bn + c];
    }

    float sp[2][2] = {}, dp[2][2] = {};
    #pragma unroll
    for (int mt = 0; mt < 2; mt++) {
        int row = bm + wm * 32 + mt * 16 + qrow;
        #pragma unroll
        for (int nt = 0; nt < 4; nt++) {
            float d0 = d[mt][nt][0], d1 = d[mt][nt][1];
            float d2 = d[mt][nt][2], d3 = d[mt][nt][3];
            int col = bn + wn * 32 + nt * 8 + qcol;
            if (row < NN) {
                __half2 h = __floats2half2_rn(d0, d1);
                *(unsigned*)&g_hh[(size_t)row * HC + col] = *(unsigned*)&h;
            }
            if (row + 8 < NN) {
                __half2 h = __floats2half2_rn(d2, d3);
                *(unsigned*)&g_hh[(size_t)(row + 8) * HC + col] = *(unsigned*)&h;
            }
            sp[mt][0] += d0 * av[nt].x + d1 * av[nt].y;
            sp[mt][1] += d2 * av[nt].x + d3 * av[nt].y;
            dp[mt][0] += d0 * dv[nt].x + d1 * dv[nt].y;
            dp[mt][1] += d2 * dv[nt].x + d3 * dv[nt].y;
        }
    }
    // quad reduce (cols within warp) then cross-warp(n) via smem
    #pragma unroll
    for (int mt = 0; mt < 2; mt++)
        #pragma unroll
        for (int h = 0; h < 2; h++) {
            sp[mt][h] += __shfl_xor_sync(0xFFFFFFFFu, sp[mt][h], 1);
            sp[mt][h] += __shfl_xor_sync(0xFFFFFFFFu, sp[mt][h], 2);
            dp[mt][h] += __shfl_xor_sync(0xFFFFFFFFu, dp[mt][h], 1);
            dp[mt][h] += __shfl_xor_sync(0xFFFFFFFFu, dp[mt][h], 2);
        }
    if ((lane & 3) == 0) {
        #pragma unroll
        for (int mt = 0; mt < 2; mt++) {
            int rl = wm * 32 + mt * 16 + qrow;
            sred[wn][rl]     = sp[mt][0];
            sred[wn][rl + 8] = sp[mt][1];
            dred[wn][rl]     = dp[mt][0];
            dred[wn][rl + 8] = dp[mt][1];
        }
    }
    __syncthreads();
    if (tid < 128) {
        int row = bm + tid;
        if (row < NN) {
            g_as[row * 4 + head] = sred[0][tid] + sred[1][tid];
            g_ad[row * 4 + head] = dred[0][tid] + dred[1][tid];
        }
    }
}

// ------- fused softmax (no max) + aggregate: one warp per destination ------
template <int ACT>
__global__ void __launch_bounds__(256)
aggregate_kernel(float* __restrict__ out, const float* __restrict__ bias,
                 int d0, int nd) {
    int d = d0 + ((blockIdx.x * blockDim.x + threadIdx.x) >> 5);
    int lane = threadIdx.x & 31;
    if (d >= d0 + nd) return;
    int beg = g_off[d], end = beg + g_cnt[d];
    float4 ad = *(const float4*)(g_ad + d * 4);

    // ---- pass 1: exp + denom (lane-strided) ----
    float d0s = 0.f, d1s = 0.f, d2s = 0.f, d3s = 0.f;
    for (int i = beg + lane; i < end; i += 32) {
        int s = g_srcs[i];
        float4 as = *(const float4*)(g_as + s * 4);
        float e0 = as.x + ad.x; e0 = e0 > 0.f ? e0 : NEG * e0; e0 = __expf(e0);
        float e1 = as.y + ad.y; e1 = e1 > 0.f ? e1 : NEG * e1; e1 = __expf(e1);
        float e2 = as.z + ad.z; e2 = e2 > 0.f ? e2 : NEG * e2; e2 = __expf(e2);
        float e3 = as.w + ad.w; e3 = e3 > 0.f ? e3 : NEG * e3; e3 = __expf(e3);
        *(float4*)(g_w + (size_t)i * 4) = make_float4(e0, e1, e2, e3);
        d0s += e0; d1s += e1; d2s += e2; d3s += e3;
    }
    #pragma unroll
    for (int o = 16; o > 0; o >>= 1) {
        d0s += __shfl_xor_sync(0xFFFFFFFFu, d0s, o);
        d1s += __shfl_xor_sync(0xFFFFFFFFu, d1s, o);
        d2s += __shfl_xor_sync(0xFFFFFFFFu, d2s, o);
        d3s += __shfl_xor_sync(0xFFFFFFFFu, d3s, o);
    }
    float i0 = 0.25f / (d0s + 1e-16f);
    float i1 = 0.25f / (d1s + 1e-16f);
    float i2 = 0.25f / (d2s + 1e-16f);
    float i3 = 0.25f / (d3s + 1e-16f);
    __syncwarp();

    // ---- pass 2: full-row LDG.128 gather, head via lane select ----
    int hsel = lane >> 3;                    // 0..3
    float acc[8];
    #pragma unroll
    for (int k = 0; k < 8; k++) acc[k] = 0.f;

    int i = beg;
    for (; i + 3 < end; i += 4) {
        int   s[4];
        float4 w[4];
        uint4 u[4];
        #pragma unroll
        for (int j = 0; j < 4; j++) s[j] = g_srcs[i + j];
        #pragma unroll
        for (int j = 0; j < 4; j++) w[j] = *(const float4*)(g_w + (size_t)(i + j) * 4);
        #pragma unroll
        for (int j = 0; j < 4; j++)
            u[j] = ((const uint4*)(g_hh + (size_t)s[j] * HC))[lane];
        #pragma unroll
        for (int j = 0; j < 4; j++) {
            float wh = hsel == 0 ? w[j].x * i0 :
                       hsel == 1 ? w[j].y * i1 :
                       hsel == 2 ? w[j].z * i2 : w[j].w * i3;
            float2 f0 = __half22float2(*(const __half2*)&u[j].x);
            float2 f1 = __half22float2(*(const __half2*)&u[j].y);
            float2 f2 = __half22float2(*(const __half2*)&u[j].z);
            float2 f3 = __half22float2(*(const __half2*)&u[j].w);
            acc[0] += f0.x * wh; acc[1] += f0.y * wh;
            acc[2] += f1.x * wh; acc[3] += f1.y * wh;
            acc[4] += f2.x * wh; acc[5] += f2.y * wh;
            acc[6] += f3.x * wh; acc[7] += f3.y * wh;
        }
    }
    for (; i < end; i++) {
        int s0 = g_srcs[i];
        float4 w0 = *(const float4*)(g_w + (size_t)i * 4);
        uint4 u0 = ((const uint4*)(g_hh + (size_t)s0 * HC))[lane];
        float wh = hsel == 0 ? w0.x * i0 :
                   hsel == 1 ? w0.y * i1 :
                   hsel == 2 ? w0.z * i2 : w0.w * i3;
        float2 f0 = __half22float2(*(const __half2*)&u0.x);
        float2 f1 = __half22float2(*(const __half2*)&u0.y);
        float2 f2 = __half22float2(*(const __half2*)&u0.z);
        float2 f3 = __half22float2(*(const __half2*)&u0.w);
        acc[0] += f0.x * wh; acc[1] += f0.y * wh;
        acc[2] += f1.x * wh; acc[3] += f1.y * wh;
        acc[4] += f2.x * wh; acc[5] += f2.y * wh;
        acc[6] += f3.x * wh; acc[7] += f3.y * wh;
    }

    #pragma unroll
    for (int k = 0; k < 8; k++) {
        acc[k] += __shfl_xor_sync(0xFFFFFFFFu, acc[k], 8);
        acc[k] += __shfl_xor_sync(0xFFFFFFFFu, acc[k], 16);
    }

    if (lane < 8) {
        float4 b0 = *(const float4*)(bias + lane * 8);
        float4 b1 = *(const float4*)(bias + lane * 8 + 4);
        float4 r0, r1;
        r0.x = acc[0] + b0.x; r0.y = acc[1] + b0.y;
        r0.z = acc[2] + b0.z; r0.w = acc[3] + b0.w;
        r1.x = acc[4] + b1.x; r1.y = acc[5] + b1.y;
        r1.z = acc[6] + b1.z; r1.w = acc[7] + b1.w;
        if (ACT) {
            r0.x = r0.x > 0.f ? r0.x : expm1f(r0.x);
            r0.y = r0.y > 0.f ? r0.y : expm1f(r0.y);
            r0.z = r0.z > 0.f ? r0.z : expm1f(r0.z);
            r0.w = r0.w > 0.f ? r0.w : expm1f(r0.w);
            r1.x = r1.x > 0.f ? r1.x : expm1f(r1.x);
            r1.y = r1.y > 0.f ? r1.y : expm1f(r1.y);
            r1.z = r1.z > 0.f ? r1.z : expm1f(r1.z);
            r1.w = r1.w > 0.f ? r1.w : expm1f(r1.w);
        }
        *(float4*)(out + (size_t)d * CC + lane * 8)     = r0;
        *(float4*)(out + (size_t)d * CC + lane * 8 + 4) = r1;
    }
}

// ---------------- host launch ----------------
extern "C" void kernel_launch(void* const* d_in, const int* in_sizes, int n_in,
                              void* d_out, int out_size) {
    const float* x      = (const float*)d_in[0];
    const void*  ei     = d_in[1];
    const float* W1     = (const float*)d_in[2];
    const float* a_src1 = (const float*)d_in[3];
    const float* a_dst1 = (const float*)d_in[4];
    const float* b1     = (const float*)d_in[5];
    const float* W2     = (const float*)d_in[6];
    const float* a_src2 = (const float*)d_in[7];
    const float* a_dst2 = (const float*)d_in[8];
    const float* b2     = (const float*)d_in[9];
    float* out = (float*)d_out;

    void* p_x2;
    cudaGetSymbolAddress(&p_x2, g_x2);
    float* x2 = (float*)p_x2;

    static cudaStream_t s2 = []{
        cudaStream_t t; cudaStreamCreateWithFlags(&t, cudaStreamNonBlocking); return t;
    }();
    static cudaEvent_t ev_fork = []{
        cudaEvent_t e; cudaEventCreateWithFlags(&e, cudaEventDisableTiming); return e;
    }();
    static cudaEvent_t ev_join = []{
        cudaEvent_t e; cudaEventCreateWithFlags(&e, cudaEventDisableTiming); return e;
    }();
    static cudaEvent_t ev_a0 = []{
        cudaEvent_t e; cudaEventCreateWithFlags(&e, cudaEventDisableTiming); return e;
    }();
    static cudaEvent_t ev_g0 = []{
        cudaEvent_t e; cudaEventCreateWithFlags(&e, cudaEventDisableTiming); return e;
    }();

    const int TB = 256;
    dim3 gemm_full((NN + 127) / 128, 4);
    dim3 gemm_h0(SPLIT / 128, 4);
    dim3 gemm_h1((NN - SPLIT + 127) / 128, 4);
    int agg_h0 = (SPLIT * 32) / TB;
    int agg_h1 = ((NN - SPLIT) * 32 + TB - 1) / TB;
    int agg_full = (NN * 32 + TB - 1) / TB;
    int edge_blocks = (ET + TB - 1) / TB;
    int node_blocks = (NN + TB - 1) / TB;

    // -------- fork: CSR build on side stream, GEMM1 on main --------
    cudaEventRecord(ev_fork, 0);
    cudaStreamWaitEvent(s2, ev_fork, 0);

    init_kernel<<<node_blocks, TB, 0, s2>>>((const int*)ei);
    hist_kernel<<<edge_blocks, TB, 0, s2>>>(ei);
    assign_offsets_kernel<<<node_blocks, TB, 0, s2>>>();
    fill_kernel<<<edge_blocks, TB, 0, s2>>>(ei);
    cudaEventRecord(ev_join, s2);

    gemm_tc_kernel<128><<<gemm_full, TB>>>(x, W1, a_src1, a_dst1, 0);

    // -------- join; pipelined agg1 / GEMM2 --------
    cudaStreamWaitEvent(0, ev_join, 0);
    aggregate_kernel<1><<<agg_h0, TB>>>(x2, b1, 0, SPLIT);
    cudaEventRecord(ev_a0, 0);
    cudaStreamWaitEvent(s2, ev_a0, 0);
    gemm_tc_kernel<64><<<gemm_h0, TB, 0, s2>>>(x2, W2, a_src2, a_dst2, 0);
    cudaEventRecord(ev_g0, s2);

    aggregate_kernel<1><<<agg_h1, TB>>>(x2, b1, SPLIT, NN - SPLIT);
    gemm_tc_kernel<64><<<gemm_h1, TB>>>(x2, W2, a_src2, a_dst2, SPLIT);

    // -------- final aggregate (needs both GEMM2 halves) --------
    cudaStreamWaitEvent(0, ev_g0, 0);
    aggregate_kernel<0><<<agg_full, TB>>>(out, b2, 0, NN);
}